// round 1
// baseline (speedup 1.0000x reference)
#include <cuda_runtime.h>
#include <cuda_bf16.h>

// Problem constants (Sopa_18897856102689)
#define L_ 512
#define B_ 64
#define D_ 256
#define N_ 256
#define P_ 6
#define E_ (2 * N_ * P_)   // 3072
#define M_ (L_ * B_)       // 32768
#define ZERO_ (-100.0f)

// Scratch for transition scores tr[(t*B + b)][e], e = n*12 + r*6 + p
// 32768 * 3072 floats = 402.7 MB (device-global scratch; no runtime alloc)
__device__ float g_tr[(size_t)M_ * (size_t)E_];

// ---------------------------------------------------------------------------
// GEMM: C[m][e] = sum_k A[m][k] * W[e][k] + bias[e]
// A = x (M x K, K=256 contiguous), W = diags (E x K, K contiguous)  -> "NT" gemm
// Tile: 128(m) x 128(e) x 16(k), 256 threads, 8x8 per-thread microtile.
// ---------------------------------------------------------------------------
__global__ __launch_bounds__(256, 2)
void sopa_gemm(const float* __restrict__ A,
               const float* __restrict__ W,
               const float* __restrict__ bias) {
    __shared__ float As[16][128];
    __shared__ float Bs[16][128];

    const int tid = threadIdx.x;          // 0..255
    const int tx  = tid & 15;             // 0..15 (e dir)
    const int ty  = tid >> 4;             // 0..15 (m dir)

    const int bm = blockIdx.y * 128;      // m offset
    const int bn = blockIdx.x * 128;      // e offset

    const float* Ablk = A + (size_t)bm * D_;
    const float* Wblk = W + (size_t)bn * D_;

    float acc[8][8];
    #pragma unroll
    for (int i = 0; i < 8; i++)
        #pragma unroll
        for (int j = 0; j < 8; j++) acc[i][j] = 0.0f;

    for (int k0 = 0; k0 < D_; k0 += 16) {
        // Load 128x16 tiles (2048 floats each = 512 float4; 2 float4/thread).
        // f = i*256 + tid  -> row = f>>2 (0..127), c4 = f&3 (which float4 in the row)
        #pragma unroll
        for (int i = 0; i < 2; i++) {
            int f   = i * 256 + tid;
            int row = f >> 2;
            int c4  = f & 3;
            float4 va = *(const float4*)(Ablk + (size_t)row * D_ + k0 + c4 * 4);
            As[c4 * 4 + 0][row] = va.x;
            As[c4 * 4 + 1][row] = va.y;
            As[c4 * 4 + 2][row] = va.z;
            As[c4 * 4 + 3][row] = va.w;
            float4 vb = *(const float4*)(Wblk + (size_t)row * D_ + k0 + c4 * 4);
            Bs[c4 * 4 + 0][row] = vb.x;
            Bs[c4 * 4 + 1][row] = vb.y;
            Bs[c4 * 4 + 2][row] = vb.z;
            Bs[c4 * 4 + 3][row] = vb.w;
        }
        __syncthreads();

        #pragma unroll
        for (int kk = 0; kk < 16; kk++) {
            float a[8], b[8];
            float4 a0 = *(const float4*)&As[kk][ty * 8];
            float4 a1 = *(const float4*)&As[kk][ty * 8 + 4];
            float4 b0 = *(const float4*)&Bs[kk][tx * 8];
            float4 b1 = *(const float4*)&Bs[kk][tx * 8 + 4];
            a[0]=a0.x; a[1]=a0.y; a[2]=a0.z; a[3]=a0.w;
            a[4]=a1.x; a[5]=a1.y; a[6]=a1.z; a[7]=a1.w;
            b[0]=b0.x; b[1]=b0.y; b[2]=b0.z; b[3]=b0.w;
            b[4]=b1.x; b[5]=b1.y; b[6]=b1.z; b[7]=b1.w;
            #pragma unroll
            for (int i = 0; i < 8; i++)
                #pragma unroll
                for (int j = 0; j < 8; j++)
                    acc[i][j] = fmaf(a[i], b[j], acc[i][j]);
        }
        __syncthreads();
    }

    // Epilogue: add bias[e], store to g_tr
    float bb[8];
    #pragma unroll
    for (int j = 0; j < 8; j++) bb[j] = bias[bn + tx * 8 + j];

    #pragma unroll
    for (int i = 0; i < 8; i++) {
        size_t rowoff = (size_t)(bm + ty * 8 + i) * E_ + bn + tx * 8;
        float4 s0, s1;
        s0.x = acc[i][0] + bb[0]; s0.y = acc[i][1] + bb[1];
        s0.z = acc[i][2] + bb[2]; s0.w = acc[i][3] + bb[3];
        s1.x = acc[i][4] + bb[4]; s1.y = acc[i][5] + bb[5];
        s1.z = acc[i][6] + bb[6]; s1.w = acc[i][7] + bb[7];
        *(float4*)(g_tr + rowoff)     = s0;
        *(float4*)(g_tr + rowoff + 4) = s1;
    }
}

// ---------------------------------------------------------------------------
// Scan: one thread per (b, n). 256 blocks x 64 threads.
// blockIdx.x = b*4 + chunk ; n = chunk*64 + threadIdx.x
// Per step reads 12 contiguous floats of tr (3 x float4, coalesced across n).
// ---------------------------------------------------------------------------
__global__ __launch_bounds__(64)
void sopa_scan(const int* __restrict__ input_len,
               const float* __restrict__ epsilon,
               float* __restrict__ out) {
    const int b = blockIdx.x >> 2;
    const int n = ((blockIdx.x & 3) << 6) | threadIdx.x;

    float eps[5];
    #pragma unroll
    for (int p = 0; p < 5; p++) eps[p] = epsilon[n * 5 + p];

    const int len    = input_len[b];
    const int endIdx = 2 + (n >> 6);    // patterns sorted by length: 64 each of len 3..6

    float h[6];
    h[0] = 0.0f;
    #pragma unroll
    for (int p = 1; p < 6; p++) h[p] = ZERO_;
    float s = ZERO_;

    const float* base = g_tr + (size_t)b * E_ + (size_t)n * 12;
    float* ob = out + (size_t)b * N_ + n;
    const size_t tstride = (size_t)B_ * E_;   // 196608 floats per timestep
    const size_t ostride = (size_t)B_ * N_;   // 16384

    #pragma unroll 4
    for (int t = 0; t < L_; t++) {
        const float4* pp = (const float4*)(base + (size_t)t * tstride);
        float4 q0 = pp[0];
        float4 q1 = pp[1];
        float4 q2 = pp[2];
        // row 0 (self-loop) = e p0..5 ; row 1 (main) = e 6..11 (p 0..4 used)
        float trS0 = q0.x, trS1 = q0.y, trS2 = q0.z, trS3 = q0.w, trS4 = q1.x, trS5 = q1.y;
        float trM0 = q1.z, trM1 = q1.w, trM2 = q2.x, trM3 = q2.y, trM4 = q2.z;

        // epsilon (state-skip) transitions
        float ae0 = fmaxf(h[0], ZERO_);
        float ae1 = fmaxf(h[1], h[0] + eps[0]);
        float ae2 = fmaxf(h[2], h[1] + eps[1]);
        float ae3 = fmaxf(h[3], h[2] + eps[2]);
        float ae4 = fmaxf(h[4], h[3] + eps[3]);
        float ae5 = fmaxf(h[5], h[4] + eps[4]);

        // main-path (advance) vs self-loop
        h[0] = fmaxf(0.0f,        ae0 + trS0);   // one_pad restart at state 0
        h[1] = fmaxf(ae0 + trM0,  ae1 + trS1);
        h[2] = fmaxf(ae1 + trM1,  ae2 + trS2);
        h[3] = fmaxf(ae2 + trM2,  ae3 + trS3);
        h[4] = fmaxf(ae3 + trM3,  ae4 + trS4);
        h[5] = fmaxf(ae4 + trM4,  ae5 + trS5);

        float ev = h[endIdx];
        if (len >= t) s = fmaxf(s, ev);
        ob[(size_t)t * ostride] = tanhf(s);
    }
}

// ---------------------------------------------------------------------------
extern "C" void kernel_launch(void* const* d_in, const int* in_sizes, int n_in,
                              void* d_out, int out_size) {
    const float* x         = (const float*)d_in[0];   // (L,B,D) f32
    const int*   input_len = (const int*)  d_in[1];   // (B,)   i32
    const float* diags     = (const float*)d_in[2];   // (E,D)  f32
    const float* bias      = (const float*)d_in[3];   // (E,1)  f32
    const float* epsilon   = (const float*)d_in[4];   // (N,P-1) f32
    float*       out       = (float*)d_out;           // (L,B,N) f32

    dim3 ggrid(E_ / 128, M_ / 128);   // (24, 256)
    sopa_gemm<<<ggrid, 256>>>(x, diags, bias);
    sopa_scan<<<256, 64>>>(input_len, epsilon, out);
}

// round 3
// speedup vs baseline: 2.1980x; 2.1980x over previous
#include <cuda_runtime.h>
#include <cuda_fp16.h>
#include <cstdint>

// Problem constants (Sopa_18897856102689)
#define L_ 512
#define B_ 64
#define D_ 256
#define N_ 256
#define P_ 6
#define E_ (2 * N_ * P_)   // 3072
#define M_ (L_ * B_)       // 32768
#define ZERO_ (-100.0f)

// Scratch: tr[(t*B + b)][e], e = n*12 + r*6 + p   (402.7 MB)
__device__ float g_tr[(size_t)M_ * (size_t)E_];

// ===========================================================================
// helpers
// ===========================================================================
__device__ __forceinline__ uint32_t smem_to_u32(const void* p) {
    uint32_t a;
    asm("{ .reg .u64 t; cvta.to.shared.u64 t, %1; cvt.u32.u64 %0, t; }"
        : "=r"(a) : "l"(p));
    return a;
}
__device__ __forceinline__ void ldsm4(uint32_t* r, uint32_t addr) {
    asm volatile("ldmatrix.sync.aligned.m8n8.x4.shared.b16 {%0,%1,%2,%3}, [%4];"
        : "=r"(r[0]), "=r"(r[1]), "=r"(r[2]), "=r"(r[3]) : "r"(addr));
}
__device__ __forceinline__ void mma16816(float* d, const uint32_t* a,
                                         uint32_t b0, uint32_t b1) {
    asm volatile(
        "mma.sync.aligned.m16n8k16.row.col.f32.f16.f16.f32 "
        "{%0,%1,%2,%3}, {%4,%5,%6,%7}, {%8,%9}, {%0,%1,%2,%3};"
        : "+f"(d[0]), "+f"(d[1]), "+f"(d[2]), "+f"(d[3])
        : "r"(a[0]), "r"(a[1]), "r"(a[2]), "r"(a[3]), "r"(b0), "r"(b1));
}
__device__ __forceinline__ uint32_t pack2(__half a, __half b) {
    __half2 t = __halves2half2(a, b);
    return *(uint32_t*)&t;
}
// swizzled byte offset within a 128x32-half tile (row stride 64B, 16B chunks)
__device__ __forceinline__ uint32_t swzc(int row, int chunk) {  // chunk 0..3
    return (uint32_t)(row * 64 + ((chunk ^ ((row >> 1) & 3)) << 4));
}

// ===========================================================================
// GEMM: C[m][e] = sum_k x[m][k]*diags[e][k] + bias[e]  (NT; K=256 contiguous)
// fp16 split (hi+lo), 3-term mma.sync, fp32 accumulate.
// BM=128, BN=128, BK=32, 512 threads, warp grid 4x4, warp tile 32x32.
// ===========================================================================
#define BM_ 128
#define BN_ 128
#define BK_ 32
#define NCHUNK_ (D_ / BK_)    // 8

#define OFF_BIAS  0
#define OFF_TILES 1024
#define ST_AHI 0
#define ST_ALO 8192
#define ST_BHI 16384
#define ST_BLO 24576
#define STAGE_SZ 32768
#define SMEM_BYTES (OFF_TILES + 2 * STAGE_SZ)   // 66560

__global__ __launch_bounds__(512, 1)
void sopa_gemm_mma(const float* __restrict__ A,
                   const float* __restrict__ W,
                   const float* __restrict__ bias) {
    extern __shared__ char smem[];
    const uint32_t sb = smem_to_u32(smem);
    const int tid  = threadIdx.x;
    const int lane = tid & 31;
    const int warp = tid >> 5;
    const int wm = (warp >> 2) * 32;     // warp row base in tile
    const int wn = (warp & 3) * 32;      // warp col base in tile

    const int bn = blockIdx.x * BN_;
    const int bm = blockIdx.y * BM_;

    if (tid < BN_) ((float*)(smem + OFF_BIAS))[tid] = bias[bn + tid];

    // per-thread global load coords: idx = tid + i*512; row = idx>>3; kq = idx&7
    const int grow = tid >> 3;
    const int gkq  = tid & 7;

    float4 ra[2], rb[2];
    {
        const float* Ap = A + (size_t)(bm + grow) * D_ + gkq * 4;
        const float* Wp = W + (size_t)(bn + grow) * D_ + gkq * 4;
        ra[0] = *(const float4*)(Ap);
        ra[1] = *(const float4*)(Ap + 64 * D_);
        rb[0] = *(const float4*)(Wp);
        rb[1] = *(const float4*)(Wp + 64 * D_);
    }

    float acc[2][4][4];
    #pragma unroll
    for (int i = 0; i < 2; i++)
        #pragma unroll
        for (int j = 0; j < 4; j++)
            #pragma unroll
            for (int k = 0; k < 4; k++) acc[i][j][k] = 0.0f;

    const int lrow = lane & 15;
    const int lsel = lane >> 4;

    for (int c = 0; c < NCHUNK_; c++) {
        const int s = c & 1;
        char* stg = smem + OFF_TILES + s * STAGE_SZ;

        // ---- convert + STS current registers ----
        #pragma unroll
        for (int i = 0; i < 2; i++) {
            const int row = grow + i * 64;
            const uint32_t off = swzc(row, gkq >> 1) + ((gkq & 1) << 3);
            float4 v = ra[i];
            __half hx = __float2half_rn(v.x), hy = __float2half_rn(v.y);
            __half hz = __float2half_rn(v.z), hw = __float2half_rn(v.w);
            uint2 hi2 = { pack2(hx, hy), pack2(hz, hw) };
            uint2 lo2 = { pack2(__float2half_rn(v.x - __half2float(hx)),
                                __float2half_rn(v.y - __half2float(hy))),
                          pack2(__float2half_rn(v.z - __half2float(hz)),
                                __float2half_rn(v.w - __half2float(hw))) };
            *(uint2*)(stg + ST_AHI + off) = hi2;
            *(uint2*)(stg + ST_ALO + off) = lo2;
            v = rb[i];
            hx = __float2half_rn(v.x); hy = __float2half_rn(v.y);
            hz = __float2half_rn(v.z); hw = __float2half_rn(v.w);
            uint2 bhi2 = { pack2(hx, hy), pack2(hz, hw) };
            uint2 blo2 = { pack2(__float2half_rn(v.x - __half2float(hx)),
                                 __float2half_rn(v.y - __half2float(hy))),
                           pack2(__float2half_rn(v.z - __half2float(hz)),
                                 __float2half_rn(v.w - __half2float(hw))) };
            *(uint2*)(stg + ST_BHI + off) = bhi2;
            *(uint2*)(stg + ST_BLO + off) = blo2;
        }
        __syncthreads();

        // ---- prefetch next chunk into registers ----
        if (c < NCHUNK_ - 1) {
            const int k0 = (c + 1) * BK_;
            const float* Ap = A + (size_t)(bm + grow) * D_ + k0 + gkq * 4;
            const float* Wp = W + (size_t)(bn + grow) * D_ + k0 + gkq * 4;
            ra[0] = *(const float4*)(Ap);
            ra[1] = *(const float4*)(Ap + 64 * D_);
            rb[0] = *(const float4*)(Wp);
            rb[1] = *(const float4*)(Wp + 64 * D_);
        }

        // ---- compute on stage s ----
        const uint32_t st = sb + OFF_TILES + s * STAGE_SZ;
        #pragma unroll
        for (int kk = 0; kk < 2; kk++) {
            const int chunk = kk * 2 + lsel;
            uint32_t aHi[2][4], aLo[2][4], bHi[2][4], bLo[2][4];
            #pragma unroll
            for (int mt = 0; mt < 2; mt++) {
                const uint32_t off = swzc(wm + mt * 16 + lrow, chunk);
                ldsm4(aHi[mt], st + ST_AHI + off);
                ldsm4(aLo[mt], st + ST_ALO + off);
            }
            #pragma unroll
            for (int ng = 0; ng < 2; ng++) {
                const uint32_t off = swzc(wn + ng * 16 + lrow, chunk);
                ldsm4(bHi[ng], st + ST_BHI + off);
                ldsm4(bLo[ng], st + ST_BLO + off);
            }
            #pragma unroll
            for (int mt = 0; mt < 2; mt++)
                #pragma unroll
                for (int nt = 0; nt < 4; nt++) {
                    const int ng = nt >> 1, sl = nt & 1;
                    mma16816(acc[mt][nt], aHi[mt], bHi[ng][sl], bHi[ng][sl + 2]);
                    mma16816(acc[mt][nt], aHi[mt], bLo[ng][sl], bLo[ng][sl + 2]);
                    mma16816(acc[mt][nt], aLo[mt], bHi[ng][sl], bHi[ng][sl + 2]);
                }
        }
        __syncthreads();
    }

    // ---- epilogue: +bias, store fp32 to g_tr ----
    const float* bs = (const float*)(smem + OFF_BIAS);
    #pragma unroll
    for (int mt = 0; mt < 2; mt++) {
        const int r0 = bm + wm + mt * 16 + (lane >> 2);
        #pragma unroll
        for (int nt = 0; nt < 4; nt++) {
            const int col = wn + nt * 8 + (lane & 3) * 2;
            const float bx = bs[col], by = bs[col + 1];
            float2 v0 = { acc[mt][nt][0] + bx, acc[mt][nt][1] + by };
            float2 v1 = { acc[mt][nt][2] + bx, acc[mt][nt][3] + by };
            *(float2*)(g_tr + (size_t)r0 * E_ + bn + col) = v0;
            *(float2*)(g_tr + (size_t)(r0 + 8) * E_ + bn + col) = v1;
        }
    }
}

// ===========================================================================
// Scan: thread per (b,n); depth-4 prefetch pipeline; cached tanh.
// ===========================================================================
__global__ __launch_bounds__(64)
void sopa_scan(const int* __restrict__ input_len,
               const float* __restrict__ epsilon,
               float* __restrict__ out) {
    const int b = blockIdx.x >> 2;
    const int n = ((blockIdx.x & 3) << 6) | threadIdx.x;

    const float e0 = epsilon[n * 5 + 0];
    const float e1 = epsilon[n * 5 + 1];
    const float e2 = epsilon[n * 5 + 2];
    const float e3 = epsilon[n * 5 + 3];
    const float e4 = epsilon[n * 5 + 4];

    const int len = input_len[b];
    const int endIdx = 2 + (n >> 6);    // 64 each of plen 3..6 -> end state 2..5

    float h0 = 0.0f, h1 = ZERO_, h2 = ZERO_, h3 = ZERO_, h4 = ZERO_, h5 = ZERO_;
    float s = ZERO_;
    float ts = -1.0f;                   // tanhf(-100) == -1.0f

    const float* base = g_tr + (size_t)b * E_ + (size_t)n * 12;
    float* ob = out + (size_t)b * N_ + n;
    const size_t tstride = (size_t)B_ * E_;
    const size_t ostride = (size_t)B_ * N_;

    float4 buf[12];
    #pragma unroll
    for (int j = 0; j < 4; j++) {
        const float4* q = (const float4*)(base + (size_t)j * tstride);
        buf[3 * j + 0] = q[0]; buf[3 * j + 1] = q[1]; buf[3 * j + 2] = q[2];
    }

    #pragma unroll 1
    for (int t0 = 0; t0 < L_; t0 += 4) {
        float4 nxt[12];
        {
            const int tn = (t0 + 4 < L_) ? (t0 + 4) : t0;   // harmless reload at end
            const float* nb = base + (size_t)tn * tstride;
            #pragma unroll
            for (int j = 0; j < 4; j++) {
                const float4* q = (const float4*)(nb + (size_t)j * tstride);
                nxt[3 * j + 0] = q[0]; nxt[3 * j + 1] = q[1]; nxt[3 * j + 2] = q[2];
            }
        }
        #pragma unroll
        for (int j = 0; j < 4; j++) {
            const int t = t0 + j;
            float4 q0 = buf[3 * j + 0];
            float4 q1 = buf[3 * j + 1];
            float4 q2 = buf[3 * j + 2];
            // row 0 (self-loop) p0..5 ; row 1 (advance) p0..4
            float trS0 = q0.x, trS1 = q0.y, trS2 = q0.z, trS3 = q0.w, trS4 = q1.x, trS5 = q1.y;
            float trM0 = q1.z, trM1 = q1.w, trM2 = q2.x, trM3 = q2.y, trM4 = q2.z;

            // epsilon transitions (h0 >= 0 always, so ae0 == h0)
            float ae0 = h0;
            float ae1 = fmaxf(h1, h0 + e0);
            float ae2 = fmaxf(h2, h1 + e1);
            float ae3 = fmaxf(h3, h2 + e2);
            float ae4 = fmaxf(h4, h3 + e3);
            float ae5 = fmaxf(h5, h4 + e4);

            h0 = fmaxf(0.0f,       ae0 + trS0);
            h1 = fmaxf(ae0 + trM0, ae1 + trS1);
            h2 = fmaxf(ae1 + trM1, ae2 + trS2);
            h3 = fmaxf(ae2 + trM2, ae3 + trS3);
            h4 = fmaxf(ae3 + trM3, ae4 + trS4);
            h5 = fmaxf(ae4 + trM4, ae5 + trS5);

            float ev = (endIdx == 2) ? h2 : (endIdx == 3) ? h3 : (endIdx == 4) ? h4 : h5;
            if (len >= t && ev > s) {
                s = ev;
                ts = tanhf(s);
            }
            ob[(size_t)t * ostride] = ts;
        }
        #pragma unroll
        for (int i = 0; i < 12; i++) buf[i] = nxt[i];
    }
}

// ===========================================================================
extern "C" void kernel_launch(void* const* d_in, const int* in_sizes, int n_in,
                              void* d_out, int out_size) {
    const float* x         = (const float*)d_in[0];   // (L,B,D) f32
    const int*   input_len = (const int*)  d_in[1];   // (B,)   i32
    const float* diags     = (const float*)d_in[2];   // (E,D)  f32
    const float* bias      = (const float*)d_in[3];   // (E,1)  f32
    const float* epsilon   = (const float*)d_in[4];   // (N,P-1) f32
    float*       out       = (float*)d_out;           // (L,B,N) f32

    cudaFuncSetAttribute(sopa_gemm_mma, cudaFuncAttributeMaxDynamicSharedMemorySize,
                         SMEM_BYTES);
    dim3 ggrid(E_ / BN_, M_ / BM_);   // (24, 256)
    sopa_gemm_mma<<<ggrid, 512, SMEM_BYTES>>>(x, diags, bias);
    sopa_scan<<<256, 64>>>(input_len, epsilon, out);
}

// round 4
// speedup vs baseline: 2.2962x; 1.0447x over previous
#include <cuda_runtime.h>
#include <cuda_fp16.h>
#include <cstdint>

// Problem constants (Sopa_18897856102689)
#define L_ 512
#define B_ 64
#define D_ 256
#define N_ 256
#define P_ 6
#define E_ (2 * N_ * P_)   // 3072
#define M_ (L_ * B_)       // 32768
#define ZERO_ (-100.0f)

// Scratch
__device__ float  g_tr[(size_t)M_ * (size_t)E_];          // 402.7 MB
__device__ __half g_xhi[(size_t)M_ * D_];                 // 16.8 MB
__device__ __half g_xlo[(size_t)M_ * D_];
__device__ __half g_whi[(size_t)E_ * D_];                 // 1.6 MB
__device__ __half g_wlo[(size_t)E_ * D_];

// ===========================================================================
// helpers
// ===========================================================================
__device__ __forceinline__ uint32_t smem_to_u32(const void* p) {
    uint32_t a;
    asm("{ .reg .u64 t; cvta.to.shared.u64 t, %1; cvt.u32.u64 %0, t; }"
        : "=r"(a) : "l"(p));
    return a;
}
__device__ __forceinline__ void ldsm4(uint32_t* r, uint32_t addr) {
    asm volatile("ldmatrix.sync.aligned.m8n8.x4.shared.b16 {%0,%1,%2,%3}, [%4];"
        : "=r"(r[0]), "=r"(r[1]), "=r"(r[2]), "=r"(r[3]) : "r"(addr));
}
__device__ __forceinline__ void mma16816(float* d, const uint32_t* a,
                                         uint32_t b0, uint32_t b1) {
    asm volatile(
        "mma.sync.aligned.m16n8k16.row.col.f32.f16.f16.f32 "
        "{%0,%1,%2,%3}, {%4,%5,%6,%7}, {%8,%9}, {%0,%1,%2,%3};"
        : "+f"(d[0]), "+f"(d[1]), "+f"(d[2]), "+f"(d[3])
        : "r"(a[0]), "r"(a[1]), "r"(a[2]), "r"(a[3]), "r"(b0), "r"(b1));
}
__device__ __forceinline__ uint32_t pack2(__half a, __half b) {
    __half2 t = __halves2half2(a, b);
    return *(uint32_t*)&t;
}
__device__ __forceinline__ void cpa16(uint32_t saddr, const void* gaddr) {
    asm volatile("cp.async.cg.shared.global [%0], [%1], 16;"
                 :: "r"(saddr), "l"(gaddr));
}
#define CP_COMMIT() asm volatile("cp.async.commit_group;" ::: "memory")
#define CP_WAIT(n)  asm volatile("cp.async.wait_group %0;" :: "n"(n) : "memory")

// swizzled byte offset within a 128x32-half tile (row stride 64B, 16B chunks)
__device__ __forceinline__ uint32_t swzc(int row, int chunk) {  // chunk 0..3
    return (uint32_t)(row * 64 + ((chunk ^ ((row >> 1) & 3)) << 4));
}

// ===========================================================================
// Convert: fp32 -> (hi fp16, lo fp16) split, vectorized float4 per thread.
// ===========================================================================
__global__ __launch_bounds__(256)
void cvt_split(const float4* __restrict__ src, uint2* __restrict__ hi,
               uint2* __restrict__ lo, int n4) {
    int i = blockIdx.x * 256 + threadIdx.x;
    if (i >= n4) return;
    float4 v = src[i];
    __half hx = __float2half_rn(v.x), hy = __float2half_rn(v.y);
    __half hz = __float2half_rn(v.z), hw = __float2half_rn(v.w);
    uint2 h2 = { pack2(hx, hy), pack2(hz, hw) };
    uint2 l2 = { pack2(__float2half_rn(v.x - __half2float(hx)),
                       __float2half_rn(v.y - __half2float(hy))),
                 pack2(__float2half_rn(v.z - __half2float(hz)),
                       __float2half_rn(v.w - __half2float(hw))) };
    hi[i] = h2;
    lo[i] = l2;
}

// ===========================================================================
// GEMM: C[m][e] = sum_k x[m][k]*diags[e][k] + bias[e]
// fp16 hi/lo preconverted; cp.async 4-stage pipeline; 3-term mma.sync.
// BM=128, BN=128, BK=32, 512 threads, warp grid 4x4, warp tile 32x32.
// ===========================================================================
#define NCHUNK_ 8            // D_/32
#define NSTAGE_ 4
#define ST_AHI 0
#define ST_ALO 8192
#define ST_BHI 16384
#define ST_BLO 24576
#define STAGE_SZ 32768
#define OFF_BIAS  0
#define OFF_TILES 1024
#define SMEM_BYTES (OFF_TILES + NSTAGE_ * STAGE_SZ)   // 132096

__device__ __forceinline__ void gemm_issue_stage(uint32_t stg, int bm, int bn,
                                                 int k0, int tid) {
    #pragma unroll
    for (int i = 0; i < 2; i++) {
        const int idx = tid + i * 512;                 // 0..1023
        const int row = idx >> 3;                      // 0..127
        const int ch8 = idx & 7;
        // split 8 sub-ids over 4 planes x ... use: plane pair by (ch8>=4)
        // simpler: each idx covers one 16B chunk in TWO planes (A or B)
        const int ch = ch8 & 3;
        const uint32_t off = swzc(row, ch);
        if (ch8 < 4) {
            const size_t go = (size_t)(bm + row) * D_ + k0 + ch * 8;
            cpa16(stg + ST_AHI + off, g_xhi + go);
            cpa16(stg + ST_ALO + off, g_xlo + go);
        } else {
            const size_t go = (size_t)(bn + row) * D_ + k0 + ch * 8;
            cpa16(stg + ST_BHI + off, g_whi + go);
            cpa16(stg + ST_BLO + off, g_wlo + go);
        }
    }
}

__global__ __launch_bounds__(512, 1)
void sopa_gemm_mma(const float* __restrict__ bias) {
    extern __shared__ char smem[];
    const uint32_t sb = smem_to_u32(smem);
    const int tid  = threadIdx.x;
    const int lane = tid & 31;
    const int warp = tid >> 5;
    const int wm = (warp >> 2) * 32;
    const int wn = (warp & 3) * 32;

    const int bn = blockIdx.x * 128;
    const int bm = blockIdx.y * 128;

    if (tid < 128) ((float*)(smem + OFF_BIAS))[tid] = bias[bn + tid];

    // prologue: fill NSTAGE_ stages
    #pragma unroll
    for (int s = 0; s < NSTAGE_; s++) {
        gemm_issue_stage(sb + OFF_TILES + s * STAGE_SZ, bm, bn, s * 32, tid);
        CP_COMMIT();
    }

    float acc[2][4][4];
    #pragma unroll
    for (int i = 0; i < 2; i++)
        #pragma unroll
        for (int j = 0; j < 4; j++)
            #pragma unroll
            for (int k = 0; k < 4; k++) acc[i][j][k] = 0.0f;

    const int lrow = lane & 15;
    const int lsel = lane >> 4;

    #pragma unroll
    for (int c = 0; c < NCHUNK_; c++) {
        CP_WAIT(NSTAGE_ - 1);
        __syncthreads();

        const uint32_t st = sb + OFF_TILES + (c & (NSTAGE_ - 1)) * STAGE_SZ;
        #pragma unroll
        for (int kk = 0; kk < 2; kk++) {
            const int chunk = kk * 2 + lsel;
            uint32_t aHi[2][4], aLo[2][4], bHi[2][4], bLo[2][4];
            #pragma unroll
            for (int mt = 0; mt < 2; mt++) {
                const uint32_t off = swzc(wm + mt * 16 + lrow, chunk);
                ldsm4(aHi[mt], st + ST_AHI + off);
                ldsm4(aLo[mt], st + ST_ALO + off);
            }
            #pragma unroll
            for (int ng = 0; ng < 2; ng++) {
                const uint32_t off = swzc(wn + ng * 16 + lrow, chunk);
                ldsm4(bHi[ng], st + ST_BHI + off);
                ldsm4(bLo[ng], st + ST_BLO + off);
            }
            #pragma unroll
            for (int mt = 0; mt < 2; mt++)
                #pragma unroll
                for (int nt = 0; nt < 4; nt++) {
                    const int ng = nt >> 1, sl = nt & 1;
                    mma16816(acc[mt][nt], aHi[mt], bHi[ng][sl], bHi[ng][sl + 2]);
                    mma16816(acc[mt][nt], aHi[mt], bLo[ng][sl], bLo[ng][sl + 2]);
                    mma16816(acc[mt][nt], aLo[mt], bHi[ng][sl], bHi[ng][sl + 2]);
                }
        }
        __syncthreads();
        if (c + NSTAGE_ < NCHUNK_)
            gemm_issue_stage(sb + OFF_TILES + (c & (NSTAGE_ - 1)) * STAGE_SZ,
                             bm, bn, (c + NSTAGE_) * 32, tid);
        CP_COMMIT();   // empty groups at tail keep wait immediate constant
    }

    // epilogue: +bias, store fp32
    const float* bs = (const float*)(smem + OFF_BIAS);
    #pragma unroll
    for (int mt = 0; mt < 2; mt++) {
        const int r0 = bm + wm + mt * 16 + (lane >> 2);
        #pragma unroll
        for (int nt = 0; nt < 4; nt++) {
            const int col = wn + nt * 8 + (lane & 3) * 2;
            const float bx = bs[col], by = bs[col + 1];
            float2 v0 = { acc[mt][nt][0] + bx, acc[mt][nt][1] + by };
            float2 v1 = { acc[mt][nt][2] + bx, acc[mt][nt][3] + by };
            *(float2*)(g_tr + (size_t)r0 * E_ + bn + col) = v0;
            *(float2*)(g_tr + (size_t)(r0 + 8) * E_ + bn + col) = v1;
        }
    }
}

// ===========================================================================
// Scan: thread per (b,n); 16-stage cp.async smem pipeline; cached tanh.
// Each thread's stage slot: 48 B (12 floats) written & read by itself.
// ===========================================================================
#define SNS_ 16
#define SSTG_ 3072                       // 64 threads * 48 B
#define SCAN_SMEM (SNS_ * SSTG_)         // 49152

__global__ __launch_bounds__(64)
void sopa_scan(const int* __restrict__ input_len,
               const float* __restrict__ epsilon,
               float* __restrict__ out) {
    extern __shared__ char ssm[];
    const uint32_t sb = smem_to_u32(ssm);
    const int tidx = threadIdx.x;
    const int b = blockIdx.x >> 2;
    const int n = ((blockIdx.x & 3) << 6) | tidx;

    const float e0 = epsilon[n * 5 + 0];
    const float e1 = epsilon[n * 5 + 1];
    const float e2 = epsilon[n * 5 + 2];
    const float e3 = epsilon[n * 5 + 3];
    const float e4 = epsilon[n * 5 + 4];

    const int len = input_len[b];
    const int endIdx = 2 + (n >> 6);

    float h0 = 0.0f, h1 = ZERO_, h2 = ZERO_, h3 = ZERO_, h4 = ZERO_, h5 = ZERO_;
    float s = ZERO_;
    float ts = -1.0f;

    const float* base = g_tr + (size_t)b * E_ + (size_t)n * 12;
    float* ob = out + (size_t)b * N_ + n;
    const size_t tstride = (size_t)B_ * E_;
    const size_t ostride = (size_t)B_ * N_;
    const uint32_t slot = sb + tidx * 48;

    // prologue: stages 0..SNS_-2
    #pragma unroll
    for (int t = 0; t < SNS_ - 1; t++) {
        const float* g = base + (size_t)t * tstride;
        const uint32_t d = slot + t * SSTG_;
        cpa16(d,      g);
        cpa16(d + 16, g + 4);
        cpa16(d + 32, g + 8);
        CP_COMMIT();
    }

    #pragma unroll 4
    for (int t = 0; t < L_; t++) {
        CP_WAIT(SNS_ - 2);
        const uint32_t d = slot + (t & (SNS_ - 1)) * SSTG_;
        float4 q0 = *(const float4*)(ssm + (d - sb));
        float4 q1 = *(const float4*)(ssm + (d - sb) + 16);
        float4 q2 = *(const float4*)(ssm + (d - sb) + 32);

        // issue stage t + SNS_-1
        if (t + SNS_ - 1 < L_) {
            const float* g = base + (size_t)(t + SNS_ - 1) * tstride;
            const uint32_t nd = slot + ((t + SNS_ - 1) & (SNS_ - 1)) * SSTG_;
            cpa16(nd,      g);
            cpa16(nd + 16, g + 4);
            cpa16(nd + 32, g + 8);
        }
        CP_COMMIT();

        float trS0 = q0.x, trS1 = q0.y, trS2 = q0.z, trS3 = q0.w, trS4 = q1.x, trS5 = q1.y;
        float trM0 = q1.z, trM1 = q1.w, trM2 = q2.x, trM3 = q2.y, trM4 = q2.z;

        float ae0 = h0;
        float ae1 = fmaxf(h1, h0 + e0);
        float ae2 = fmaxf(h2, h1 + e1);
        float ae3 = fmaxf(h3, h2 + e2);
        float ae4 = fmaxf(h4, h3 + e3);
        float ae5 = fmaxf(h5, h4 + e4);

        h0 = fmaxf(0.0f,       ae0 + trS0);
        h1 = fmaxf(ae0 + trM0, ae1 + trS1);
        h2 = fmaxf(ae1 + trM1, ae2 + trS2);
        h3 = fmaxf(ae2 + trM2, ae3 + trS3);
        h4 = fmaxf(ae3 + trM3, ae4 + trS4);
        h5 = fmaxf(ae4 + trM4, ae5 + trS5);

        float ev = (endIdx == 2) ? h2 : (endIdx == 3) ? h3 : (endIdx == 4) ? h4 : h5;
        if (len >= t && ev > s) {
            s = ev;
            ts = tanhf(s);
        }
        ob[(size_t)t * ostride] = ts;
    }
}

// ===========================================================================
extern "C" void kernel_launch(void* const* d_in, const int* in_sizes, int n_in,
                              void* d_out, int out_size) {
    const float* x         = (const float*)d_in[0];   // (L,B,D) f32
    const int*   input_len = (const int*)  d_in[1];   // (B,)   i32
    const float* diags     = (const float*)d_in[2];   // (E,D)  f32
    const float* bias      = (const float*)d_in[3];   // (E,1)  f32
    const float* epsilon   = (const float*)d_in[4];   // (N,P-1) f32
    float*       out       = (float*)d_out;           // (L,B,N) f32

    cudaFuncSetAttribute(sopa_gemm_mma, cudaFuncAttributeMaxDynamicSharedMemorySize,
                         SMEM_BYTES);
    cudaFuncSetAttribute(sopa_scan, cudaFuncAttributeMaxDynamicSharedMemorySize,
                         SCAN_SMEM);

    __half *xhi, *xlo, *whi, *wlo;
    cudaGetSymbolAddress((void**)&xhi, g_xhi);
    cudaGetSymbolAddress((void**)&xlo, g_xlo);
    cudaGetSymbolAddress((void**)&whi, g_whi);
    cudaGetSymbolAddress((void**)&wlo, g_wlo);

    const int n4x = M_ * D_ / 4;    // 2097152
    const int n4w = E_ * D_ / 4;    // 196608
    cvt_split<<<(n4x + 255) / 256, 256>>>((const float4*)x, (uint2*)xhi, (uint2*)xlo, n4x);
    cvt_split<<<(n4w + 255) / 256, 256>>>((const float4*)diags, (uint2*)whi, (uint2*)wlo, n4w);

    dim3 ggrid(E_ / 128, M_ / 128);   // (24, 256)
    sopa_gemm_mma<<<ggrid, 512, SMEM_BYTES>>>(bias);
    sopa_scan<<<256, 64, SCAN_SMEM>>>(input_len, epsilon, out);
}

// round 6
// speedup vs baseline: 2.4272x; 1.0570x over previous
#include <cuda_runtime.h>
#include <cuda_fp16.h>
#include <cstdint>

// Problem constants (Sopa_18897856102689)
#define L_ 512
#define B_ 64
#define D_ 256
#define N_ 256
#define P_ 6
#define M_ (L_ * B_)       // 32768
#define ZERO_ (-100.0f)

// Packed transition columns: pattern-length groups g=0..3 (plen=3..6, 64 each)
// group width w = 2*plen-1 = {5,7,9,11}; packed E2 = 64*(5+7+9+11) = 2048
// padded store widths wp = {8,8,12,12}; padded E2P = 64*(8+8+12+12) = 2560
#define E2_  2048
#define E2P_ 2560
__device__ const int GP_[4] = {0, 512, 1024, 1792};    // padded group bases

// Scratch
__device__ float  g_tr[(size_t)M_ * (size_t)E2P_];     // 335.5 MB (padded layout)
__device__ __half g_xhi[(size_t)M_ * D_];              // 16.8 MB
__device__ __half g_xlo[(size_t)M_ * D_];
__device__ __half g_whi[(size_t)E2_ * D_];             // 1.05 MB (packed rows)
__device__ __half g_wlo[(size_t)E2_ * D_];
__device__ float  g_bias2[E2_];

// ===========================================================================
// helpers
// ===========================================================================
__device__ __forceinline__ uint32_t smem_to_u32(const void* p) {
    uint32_t a;
    asm("{ .reg .u64 t; cvta.to.shared.u64 t, %1; cvt.u32.u64 %0, t; }"
        : "=r"(a) : "l"(p));
    return a;
}
__device__ __forceinline__ void ldsm4(uint32_t* r, uint32_t addr) {
    asm volatile("ldmatrix.sync.aligned.m8n8.x4.shared.b16 {%0,%1,%2,%3}, [%4];"
        : "=r"(r[0]), "=r"(r[1]), "=r"(r[2]), "=r"(r[3]) : "r"(addr));
}
__device__ __forceinline__ void mma16816(float* d, const uint32_t* a,
                                         uint32_t b0, uint32_t b1) {
    asm volatile(
        "mma.sync.aligned.m16n8k16.row.col.f32.f16.f16.f32 "
        "{%0,%1,%2,%3}, {%4,%5,%6,%7}, {%8,%9}, {%0,%1,%2,%3};"
        : "+f"(d[0]), "+f"(d[1]), "+f"(d[2]), "+f"(d[3])
        : "r"(a[0]), "r"(a[1]), "r"(a[2]), "r"(a[3]), "r"(b0), "r"(b1));
}
__device__ __forceinline__ uint32_t pack2(__half a, __half b) {
    __half2 t = __halves2half2(a, b);
    return *(uint32_t*)&t;
}
__device__ __forceinline__ void cpa16(uint32_t saddr, const void* gaddr) {
    asm volatile("cp.async.cg.shared.global [%0], [%1], 16;"
                 :: "r"(saddr), "l"(gaddr));
}
#define CP_COMMIT() asm volatile("cp.async.commit_group;" ::: "memory")
#define CP_WAIT(n)  asm volatile("cp.async.wait_group %0;" :: "n"(n) : "memory")

// swizzled byte offset within a 128x32-half tile (row stride 64B, 16B chunks)
__device__ __forceinline__ uint32_t swzc(int row, int chunk) {  // chunk 0..3
    return (uint32_t)(row * 64 + ((chunk ^ ((row >> 1) & 3)) << 4));
}

// packed column e2 -> padded column offset
__device__ __forceinline__ int packed_off(int e2) {
    int base, w, wp, gp;
    if (e2 < 320)       { base = 0;    w = 5;  wp = 8;  gp = 0; }
    else if (e2 < 768)  { base = 320;  w = 7;  wp = 8;  gp = 512; }
    else if (e2 < 1344) { base = 768;  w = 9;  wp = 12; gp = 1024; }
    else                { base = 1344; w = 11; wp = 12; gp = 1792; }
    int r = e2 - base;
    int nl = r / w;
    int j = r - nl * w;
    return gp + nl * wp + j;
}

// ===========================================================================
// Convert x: fp32 -> (hi fp16, lo fp16)
// ===========================================================================
__global__ __launch_bounds__(256)
void cvt_split(const float4* __restrict__ src, uint2* __restrict__ hi,
               uint2* __restrict__ lo, int n4) {
    int i = blockIdx.x * 256 + threadIdx.x;
    if (i >= n4) return;
    float4 v = src[i];
    __half hx = __float2half_rn(v.x), hy = __float2half_rn(v.y);
    __half hz = __float2half_rn(v.z), hw = __float2half_rn(v.w);
    uint2 h2 = { pack2(hx, hy), pack2(hz, hw) };
    uint2 l2 = { pack2(__float2half_rn(v.x - __half2float(hx)),
                       __float2half_rn(v.y - __half2float(hy))),
                 pack2(__float2half_rn(v.z - __half2float(hz)),
                       __float2half_rn(v.w - __half2float(hw))) };
    hi[i] = h2;
    lo[i] = l2;
}

// ===========================================================================
// Repack W: gather needed transition rows into packed (E2 x D) hi/lo + bias
// Column j order per pattern: [self p=0..plen-1, main p=0..plen-2]
// ===========================================================================
__global__ __launch_bounds__(64)
void repack_w(const float* __restrict__ diags, const float* __restrict__ bias) {
    const int e2 = blockIdx.x;
    int g, base;
    if (e2 < 320)       { g = 0; base = 0; }
    else if (e2 < 768)  { g = 1; base = 320; }
    else if (e2 < 1344) { g = 2; base = 768; }
    else                { g = 3; base = 1344; }
    const int plen = g + 3;
    const int w = 2 * plen - 1;
    const int r0 = e2 - base;
    const int nl = r0 / w;
    const int j = r0 - nl * w;
    const int n = (g << 6) + nl;
    const int e_orig = n * 12 + (j < plen ? j : 6 + (j - plen));

    const int t = threadIdx.x;      // 0..63 (float4 index of the 256-row)
    float4 v = ((const float4*)(diags + (size_t)e_orig * D_))[t];
    __half hx = __float2half_rn(v.x), hy = __float2half_rn(v.y);
    __half hz = __float2half_rn(v.z), hw = __float2half_rn(v.w);
    uint2 h2 = { pack2(hx, hy), pack2(hz, hw) };
    uint2 l2 = { pack2(__float2half_rn(v.x - __half2float(hx)),
                       __float2half_rn(v.y - __half2float(hy))),
                 pack2(__float2half_rn(v.z - __half2float(hz)),
                       __float2half_rn(v.w - __half2float(hw))) };
    ((uint2*)(g_whi + (size_t)e2 * D_))[t] = h2;
    ((uint2*)(g_wlo + (size_t)e2 * D_))[t] = l2;
    if (t == 0) g_bias2[e2] = bias[e_orig];
}

// ===========================================================================
// GEMM: C[m][e2] = sum_k x[m][k]*Wpacked[e2][k] + bias2[e2]
// fp16 hi/lo, 3-term mma.sync, cp.async 4-stage, single-sync mainloop.
// BM=128, BN=128, BK=32, 512 threads, warp grid 4x4, warp tile 32x32.
// Output written to PADDED layout g_tr[m][E2P] (scalar stores — offsets may
// be odd in the padded layout, so no vector stores here).
// ===========================================================================
#define NCHUNK_ 8
#define NSTAGE_ 4
#define ST_AHI 0
#define ST_ALO 8192
#define ST_BHI 16384
#define ST_BLO 24576
#define STAGE_SZ 32768
#define OFF_BIAS  0
#define OFF_TILES 1024
#define SMEM_BYTES (OFF_TILES + NSTAGE_ * STAGE_SZ)   // 132096

__device__ __forceinline__ void gemm_issue_stage(uint32_t stg, int bm, int bn,
                                                 int k0, int tid) {
    #pragma unroll
    for (int i = 0; i < 2; i++) {
        const int idx = tid + i * 512;                 // 0..1023
        const int row = idx >> 3;                      // 0..127
        const int ch8 = idx & 7;
        const int ch = ch8 & 3;
        const uint32_t off = swzc(row, ch);
        if (ch8 < 4) {
            const size_t go = (size_t)(bm + row) * D_ + k0 + ch * 8;
            cpa16(stg + ST_AHI + off, g_xhi + go);
            cpa16(stg + ST_ALO + off, g_xlo + go);
        } else {
            const size_t go = (size_t)(bn + row) * D_ + k0 + ch * 8;
            cpa16(stg + ST_BHI + off, g_whi + go);
            cpa16(stg + ST_BLO + off, g_wlo + go);
        }
    }
}

__global__ __launch_bounds__(512, 1)
void sopa_gemm_mma() {
    extern __shared__ char smem[];
    const uint32_t sb = smem_to_u32(smem);
    const int tid  = threadIdx.x;
    const int lane = tid & 31;
    const int warp = tid >> 5;
    const int wm = (warp >> 2) * 32;
    const int wn = (warp & 3) * 32;

    const int bn = blockIdx.x * 128;
    const int bm = blockIdx.y * 128;

    if (tid < 128) ((float*)(smem + OFF_BIAS))[tid] = g_bias2[bn + tid];

    // prologue: NSTAGE_-1 stages
    #pragma unroll
    for (int s = 0; s < NSTAGE_ - 1; s++) {
        gemm_issue_stage(sb + OFF_TILES + s * STAGE_SZ, bm, bn, s * 32, tid);
        CP_COMMIT();
    }

    float acc[2][4][4];
    #pragma unroll
    for (int i = 0; i < 2; i++)
        #pragma unroll
        for (int j = 0; j < 4; j++)
            #pragma unroll
            for (int k = 0; k < 4; k++) acc[i][j][k] = 0.0f;

    const int lrow = lane & 15;
    const int lsel = lane >> 4;

    #pragma unroll
    for (int c = 0; c < NCHUNK_; c++) {
        CP_WAIT(NSTAGE_ - 2);
        __syncthreads();

        if (c + NSTAGE_ - 1 < NCHUNK_)
            gemm_issue_stage(sb + OFF_TILES + ((c + NSTAGE_ - 1) & (NSTAGE_ - 1)) * STAGE_SZ,
                             bm, bn, (c + NSTAGE_ - 1) * 32, tid);
        CP_COMMIT();

        const uint32_t st = sb + OFF_TILES + (c & (NSTAGE_ - 1)) * STAGE_SZ;
        #pragma unroll
        for (int kk = 0; kk < 2; kk++) {
            const int chunk = kk * 2 + lsel;
            uint32_t aHi[2][4], aLo[2][4], bHi[2][4], bLo[2][4];
            #pragma unroll
            for (int mt = 0; mt < 2; mt++) {
                const uint32_t off = swzc(wm + mt * 16 + lrow, chunk);
                ldsm4(aHi[mt], st + ST_AHI + off);
                ldsm4(aLo[mt], st + ST_ALO + off);
            }
            #pragma unroll
            for (int ng = 0; ng < 2; ng++) {
                const uint32_t off = swzc(wn + ng * 16 + lrow, chunk);
                ldsm4(bHi[ng], st + ST_BHI + off);
                ldsm4(bLo[ng], st + ST_BLO + off);
            }
            #pragma unroll
            for (int mt = 0; mt < 2; mt++)
                #pragma unroll
                for (int nt = 0; nt < 4; nt++) {
                    const int ng = nt >> 1, sl = nt & 1;
                    mma16816(acc[mt][nt], aHi[mt], bHi[ng][sl], bHi[ng][sl + 2]);
                    mma16816(acc[mt][nt], aHi[mt], bLo[ng][sl], bLo[ng][sl + 2]);
                    mma16816(acc[mt][nt], aLo[mt], bHi[ng][sl], bHi[ng][sl + 2]);
                }
        }
    }

    // epilogue: +bias, scalar stores into the padded layout
    const float* bs = (const float*)(smem + OFF_BIAS);
    #pragma unroll
    for (int nt = 0; nt < 4; nt++) {
        const int col = wn + nt * 8 + (lane & 3) * 2;
        const int e2 = bn + col;
        const int po0 = packed_off(e2);
        const int po1 = packed_off(e2 + 1);
        const float bx = bs[col], by = bs[col + 1];
        #pragma unroll
        for (int mt = 0; mt < 2; mt++) {
            const int r0 = bm + wm + mt * 16 + (lane >> 2);
            float* d0 = g_tr + (size_t)r0 * E2P_;
            float* d1 = g_tr + (size_t)(r0 + 8) * E2P_;
            d0[po0] = acc[mt][nt][0] + bx;
            d0[po1] = acc[mt][nt][1] + by;
            d1[po0] = acc[mt][nt][2] + bx;
            d1[po1] = acc[mt][nt][3] + by;
        }
    }
}

// ===========================================================================
// Scan: thread per (b,n); templated on pattern length; 16-stage cp.async.
// ===========================================================================
#define SNS_ 16
#define SSTG_ 3072                       // 64 threads * 48 B
#define SCAN_SMEM (SNS_ * SSTG_)         // 49152

template<int PLEN, int NQ>
__device__ __forceinline__ void scan_body(int b, int n, int colpad,
                                          const int* __restrict__ input_len,
                                          const float* __restrict__ epsilon,
                                          float* __restrict__ out,
                                          char* ssm, uint32_t sb, int tidx) {
    float eps[PLEN - 1];
    #pragma unroll
    for (int i = 0; i < PLEN - 1; i++) eps[i] = epsilon[n * 5 + i];

    const int len = input_len[b];

    float h[PLEN];
    h[0] = 0.0f;
    #pragma unroll
    for (int i = 1; i < PLEN; i++) h[i] = ZERO_;
    float s = ZERO_;
    float ts = -1.0f;                   // tanhf(-100) == -1

    const float* base = g_tr + (size_t)b * E2P_ + colpad;
    float* ob = out + (size_t)b * N_ + n;
    const size_t tstride = (size_t)B_ * E2P_;
    const size_t ostride = (size_t)B_ * N_;
    const uint32_t slot = sb + tidx * 48;

    #pragma unroll
    for (int t = 0; t < SNS_ - 1; t++) {
        const float* g = base + (size_t)t * tstride;
        const uint32_t d = slot + t * SSTG_;
        #pragma unroll
        for (int q = 0; q < NQ; q++) cpa16(d + q * 16, g + q * 4);
        CP_COMMIT();
    }

    #pragma unroll 4
    for (int t = 0; t < L_; t++) {
        CP_WAIT(SNS_ - 2);
        const uint32_t doff = (uint32_t)(tidx * 48) + (t & (SNS_ - 1)) * SSTG_;
        float q[NQ * 4];
        #pragma unroll
        for (int i = 0; i < NQ; i++) {
            float4 v = *(const float4*)(ssm + doff + i * 16);
            q[i * 4 + 0] = v.x; q[i * 4 + 1] = v.y;
            q[i * 4 + 2] = v.z; q[i * 4 + 3] = v.w;
        }
        if (t + SNS_ - 1 < L_) {
            const float* g = base + (size_t)(t + SNS_ - 1) * tstride;
            const uint32_t nd = slot + ((t + SNS_ - 1) & (SNS_ - 1)) * SSTG_;
            #pragma unroll
            for (int qq = 0; qq < NQ; qq++) cpa16(nd + qq * 16, g + qq * 4);
        }
        CP_COMMIT();

        // q[0..PLEN-1] = self-loop, q[PLEN..2*PLEN-2] = advance
        float ae[PLEN];
        ae[0] = h[0];
        #pragma unroll
        for (int i = 1; i < PLEN; i++) ae[i] = fmaxf(h[i], h[i - 1] + eps[i - 1]);

        h[0] = fmaxf(0.0f, ae[0] + q[0]);
        #pragma unroll
        for (int i = 1; i < PLEN; i++)
            h[i] = fmaxf(ae[i - 1] + q[PLEN + i - 1], ae[i] + q[i]);

        float ev = h[PLEN - 1];
        if (len >= t && ev > s) {
            s = ev;
            ts = tanhf(s);
        }
        ob[(size_t)t * ostride] = ts;
    }
}

__global__ __launch_bounds__(64)
void sopa_scan(const int* __restrict__ input_len,
               const float* __restrict__ epsilon,
               float* __restrict__ out) {
    extern __shared__ char ssm[];
    const uint32_t sb = smem_to_u32(ssm);
    const int tidx = threadIdx.x;
    const int b = blockIdx.x >> 2;
    const int g = blockIdx.x & 3;
    const int n = (g << 6) | tidx;

    switch (g) {
        case 0: scan_body<3, 2>(b, n, 0    + tidx * 8,  input_len, epsilon, out, ssm, sb, tidx); break;
        case 1: scan_body<4, 2>(b, n, 512  + tidx * 8,  input_len, epsilon, out, ssm, sb, tidx); break;
        case 2: scan_body<5, 3>(b, n, 1024 + tidx * 12, input_len, epsilon, out, ssm, sb, tidx); break;
        default: scan_body<6, 3>(b, n, 1792 + tidx * 12, input_len, epsilon, out, ssm, sb, tidx); break;
    }
}

// ===========================================================================
extern "C" void kernel_launch(void* const* d_in, const int* in_sizes, int n_in,
                              void* d_out, int out_size) {
    const float* x         = (const float*)d_in[0];   // (L,B,D) f32
    const int*   input_len = (const int*)  d_in[1];   // (B,)   i32
    const float* diags     = (const float*)d_in[2];   // (E,D)  f32
    const float* bias      = (const float*)d_in[3];   // (E,1)  f32
    const float* epsilon   = (const float*)d_in[4];   // (N,P-1) f32
    float*       out       = (float*)d_out;           // (L,B,N) f32

    cudaFuncSetAttribute(sopa_gemm_mma, cudaFuncAttributeMaxDynamicSharedMemorySize,
                         SMEM_BYTES);
    cudaFuncSetAttribute(sopa_scan, cudaFuncAttributeMaxDynamicSharedMemorySize,
                         SCAN_SMEM);

    __half *xhi, *xlo;
    cudaGetSymbolAddress((void**)&xhi, g_xhi);
    cudaGetSymbolAddress((void**)&xlo, g_xlo);

    const int n4x = M_ * D_ / 4;    // 2097152
    cvt_split<<<(n4x + 255) / 256, 256>>>((const float4*)x, (uint2*)xhi, (uint2*)xlo, n4x);
    repack_w<<<E2_, 64>>>(diags, bias);

    dim3 ggrid(E2_ / 128, M_ / 128);   // (16, 256)
    sopa_gemm_mma<<<ggrid, 512, SMEM_BYTES>>>();
    sopa_scan<<<256, 64, SCAN_SMEM>>>(input_len, epsilon, out);
}

// round 7
// speedup vs baseline: 2.4872x; 1.0247x over previous
#include <cuda_runtime.h>
#include <cuda_fp16.h>
#include <cstdint>

// Problem constants (Sopa_18897856102689)
#define L_ 512
#define B_ 64
#define D_ 256
#define N_ 256
#define P_ 6
#define M_ (L_ * B_)       // 32768
#define ZERO_ (-100.0f)

// Packed transition columns: pattern-length groups g=0..3 (plen=3..6, 64 each)
// packed E2 = 64*(5+7+9+11) = 2048 ; padded widths {8,8,12,12} -> E2P = 2560
#define E2_  2048
#define E2P_ 2560

// Scratch. x/W operands stored in TILE-IMAGE layout: tile = (rowblock of 128,
// kchunk of 32 halves) = 8192 contiguous bytes, identical to the smem stage
// plane image (so a stage fill is a plain 8 KB bulk memcpy).
__device__ float  g_tr[(size_t)M_ * (size_t)E2P_];              // 335.5 MB
__device__ __align__(128) __half g_xhi[(size_t)M_ * D_];        // 16.8 MB
__device__ __align__(128) __half g_xlo[(size_t)M_ * D_];
__device__ __align__(128) __half g_whi[(size_t)E2_ * D_];       // 1.05 MB
__device__ __align__(128) __half g_wlo[(size_t)E2_ * D_];
__device__ float  g_bias2[E2_];

// ===========================================================================
// helpers
// ===========================================================================
__device__ __forceinline__ uint32_t smem_to_u32(const void* p) {
    uint32_t a;
    asm("{ .reg .u64 t; cvta.to.shared.u64 t, %1; cvt.u32.u64 %0, t; }"
        : "=r"(a) : "l"(p));
    return a;
}
__device__ __forceinline__ void ldsm4(uint32_t* r, uint32_t addr) {
    asm volatile("ldmatrix.sync.aligned.m8n8.x4.shared.b16 {%0,%1,%2,%3}, [%4];"
        : "=r"(r[0]), "=r"(r[1]), "=r"(r[2]), "=r"(r[3]) : "r"(addr));
}
__device__ __forceinline__ void mma16816(float* d, const uint32_t* a,
                                         uint32_t b0, uint32_t b1) {
    asm volatile(
        "mma.sync.aligned.m16n8k16.row.col.f32.f16.f16.f32 "
        "{%0,%1,%2,%3}, {%4,%5,%6,%7}, {%8,%9}, {%0,%1,%2,%3};"
        : "+f"(d[0]), "+f"(d[1]), "+f"(d[2]), "+f"(d[3])
        : "r"(a[0]), "r"(a[1]), "r"(a[2]), "r"(a[3]), "r"(b0), "r"(b1));
}
__device__ __forceinline__ uint32_t pack2(__half a, __half b) {
    __half2 t = __halves2half2(a, b);
    return *(uint32_t*)&t;
}
__device__ __forceinline__ void cpa16(uint32_t saddr, const void* gaddr) {
    asm volatile("cp.async.cg.shared.global [%0], [%1], 16;"
                 :: "r"(saddr), "l"(gaddr));
}
#define CP_COMMIT() asm volatile("cp.async.commit_group;" ::: "memory")
#define CP_WAIT(n)  asm volatile("cp.async.wait_group %0;" :: "n"(n) : "memory")

// bulk async copy global -> shared, mbarrier completion (sm_90 PTX)
__device__ __forceinline__ void bulk_g2s(uint32_t saddr, const void* gaddr,
                                         uint32_t bytes, uint32_t mbar) {
    asm volatile(
        "cp.async.bulk.shared::cluster.global.mbarrier::complete_tx::bytes "
        "[%0], [%1], %2, [%3];"
        :: "r"(saddr), "l"(gaddr), "r"(bytes), "r"(mbar) : "memory");
}
#define MBARRIER_INIT(mbar, cnt) \
    asm volatile("mbarrier.init.shared.b64 [%0], %1;" \
                 :: "r"((uint32_t)(mbar)), "r"((uint32_t)(cnt)) : "memory")
#define MBAR_EXPECT_TX(mbar, bytes) \
    asm volatile("mbarrier.arrive.expect_tx.shared.b64 _, [%0], %1;" \
                 :: "r"((uint32_t)(mbar)), "r"((uint32_t)(bytes)) : "memory")
#define MBARRIER_WAIT_PARITY(mbar, par) do {                                   \
    uint32_t _m = (uint32_t)(mbar);                                            \
    uint32_t _p = (uint32_t)(par);                                             \
    uint32_t _d;                                                               \
    asm volatile("{\n\t.reg .pred p;\n\t"                                      \
        "mbarrier.try_wait.parity.acquire.cta.shared::cta.b64 p, [%1], %2;\n\t"\
        "selp.b32 %0, 1, 0, p;\n\t}"                                           \
        : "=r"(_d) : "r"(_m), "r"(_p) : "memory");                             \
    if (!_d) {                                                                 \
        asm volatile("{\n\t.reg .pred P1;\n\t"                                 \
            "WAIT_LOOP_%=:\n\t"                                                \
            "mbarrier.try_wait.parity.acquire.cta.shared::cta.b64 P1, [%0], %1, 0x989680;\n\t" \
            "@P1 bra.uni WAIT_DONE_%=;\n\t"                                    \
            "bra.uni WAIT_LOOP_%=;\n\t"                                        \
            "WAIT_DONE_%=:\n\t}"                                               \
            :: "r"(_m), "r"(_p) : "memory");                                   \
    }                                                                          \
} while (0)

// swizzled byte offset within a 128x32-half tile image (row=64B, 16B granule)
__device__ __forceinline__ uint32_t swzc(int row, int chunk) {  // chunk 0..3
    return (uint32_t)(row * 64 + ((chunk ^ ((row >> 1) & 3)) << 4));
}

// packed column e2 -> padded column offset
__device__ __forceinline__ int packed_off(int e2) {
    int base, w, wp, gp;
    if (e2 < 320)       { base = 0;    w = 5;  wp = 8;  gp = 0; }
    else if (e2 < 768)  { base = 320;  w = 7;  wp = 8;  gp = 512; }
    else if (e2 < 1344) { base = 768;  w = 9;  wp = 12; gp = 1024; }
    else                { base = 1344; w = 11; wp = 12; gp = 1792; }
    int r = e2 - base;
    int nl = r / w;
    int j = r - nl * w;
    return gp + nl * wp + j;
}

// ===========================================================================
// Convert x: fp32 -> (hi,lo) fp16 in TILE-IMAGE layout.
// Thread handles 8 consecutive k: i = m*32 + kq ; kc=kq>>2, ch=kq&3.
// dst byte = tile(m>>7, kc)*8192 + swzc(m&127, ch)
// ===========================================================================
__global__ __launch_bounds__(256)
void cvt_split_tiled(const float* __restrict__ x) {
    const int i = blockIdx.x * 256 + threadIdx.x;   // 0 .. M_*32-1
    const int m  = i >> 5;
    const int kq = i & 31;
    const float4 v0 = *(const float4*)(x + (size_t)m * D_ + kq * 8);
    const float4 v1 = *(const float4*)(x + (size_t)m * D_ + kq * 8 + 4);
    __half h0 = __float2half_rn(v0.x), h1 = __float2half_rn(v0.y);
    __half h2 = __float2half_rn(v0.z), h3 = __float2half_rn(v0.w);
    __half h4 = __float2half_rn(v1.x), h5 = __float2half_rn(v1.y);
    __half h6 = __float2half_rn(v1.z), h7 = __float2half_rn(v1.w);
    uint4 hi = { pack2(h0, h1), pack2(h2, h3), pack2(h4, h5), pack2(h6, h7) };
    uint4 lo = { pack2(__float2half_rn(v0.x - __half2float(h0)),
                       __float2half_rn(v0.y - __half2float(h1))),
                 pack2(__float2half_rn(v0.z - __half2float(h2)),
                       __float2half_rn(v0.w - __half2float(h3))),
                 pack2(__float2half_rn(v1.x - __half2float(h4)),
                       __float2half_rn(v1.y - __half2float(h5))),
                 pack2(__float2half_rn(v1.z - __half2float(h6)),
                       __float2half_rn(v1.w - __half2float(h7))) };
    const size_t off = (size_t)((m >> 7) * 8 + (kq >> 2)) * 8192
                     + swzc(m & 127, kq & 3);
    *(uint4*)((char*)g_xhi + off) = hi;
    *(uint4*)((char*)g_xlo + off) = lo;
}

// ===========================================================================
// Repack W into packed rows (E2) with TILE-IMAGE layout + bias gather.
// grid = E2_ blocks, 32 threads; thread t handles 8 k-values.
// ===========================================================================
__global__ __launch_bounds__(32)
void repack_w_tiled(const float* __restrict__ diags, const float* __restrict__ bias) {
    const int e2 = blockIdx.x;
    int g, base;
    if (e2 < 320)       { g = 0; base = 0; }
    else if (e2 < 768)  { g = 1; base = 320; }
    else if (e2 < 1344) { g = 2; base = 768; }
    else                { g = 3; base = 1344; }
    const int plen = g + 3;
    const int w = 2 * plen - 1;
    const int r0 = e2 - base;
    const int nl = r0 / w;
    const int j = r0 - nl * w;
    const int n = (g << 6) + nl;
    const int e_orig = n * 12 + (j < plen ? j : 6 + (j - plen));

    const int t = threadIdx.x;                      // 0..31 (8-half chunks)
    const float4 v0 = *(const float4*)(diags + (size_t)e_orig * D_ + t * 8);
    const float4 v1 = *(const float4*)(diags + (size_t)e_orig * D_ + t * 8 + 4);
    __half h0 = __float2half_rn(v0.x), h1 = __float2half_rn(v0.y);
    __half h2 = __float2half_rn(v0.z), h3 = __float2half_rn(v0.w);
    __half h4 = __float2half_rn(v1.x), h5 = __float2half_rn(v1.y);
    __half h6 = __float2half_rn(v1.z), h7 = __float2half_rn(v1.w);
    uint4 hi = { pack2(h0, h1), pack2(h2, h3), pack2(h4, h5), pack2(h6, h7) };
    uint4 lo = { pack2(__float2half_rn(v0.x - __half2float(h0)),
                       __float2half_rn(v0.y - __half2float(h1))),
                 pack2(__float2half_rn(v0.z - __half2float(h2)),
                       __float2half_rn(v0.w - __half2float(h3))),
                 pack2(__float2half_rn(v1.x - __half2float(h4)),
                       __float2half_rn(v1.y - __half2float(h5))),
                 pack2(__float2half_rn(v1.z - __half2float(h6)),
                       __float2half_rn(v1.w - __half2float(h7))) };
    const size_t off = (size_t)((e2 >> 7) * 8 + (t >> 2)) * 8192
                     + swzc(e2 & 127, t & 3);
    *(uint4*)((char*)g_whi + off) = hi;
    *(uint4*)((char*)g_wlo + off) = lo;
    if (t == 0) g_bias2[e2] = bias[e_orig];
}

// ===========================================================================
// GEMM: C[m][e2] = sum_k x[m][k]*Wpacked[e2][k] + bias2[e2]
// Stages filled with cp.async.bulk (4 x 8KB per stage, tid0-issued, mbarrier).
// BM=128, BN=128, BK=32, 512 threads, warp grid 4x4, warp tile 32x32.
// ===========================================================================
#define NCHUNK_ 8
#define NSTAGE_ 4
#define ST_AHI 0
#define ST_ALO 8192
#define ST_BHI 16384
#define ST_BLO 24576
#define STAGE_SZ 32768
#define OFF_BIAS  0
#define OFF_MBAR  512
#define OFF_TILES 1024
#define SMEM_BYTES (OFF_TILES + NSTAGE_ * STAGE_SZ)   // 132096

__device__ __forceinline__ void gemm_issue_bulk(uint32_t sb, int slot,
                                                int chunk, int mb, int nb) {
    const uint32_t stg = sb + OFF_TILES + slot * STAGE_SZ;
    const uint32_t mbar = sb + OFF_MBAR + slot * 8;
    MBAR_EXPECT_TX(mbar, 4 * 8192);
    const size_t at = (size_t)(mb * 8 + chunk) * 8192;
    const size_t bt = (size_t)(nb * 8 + chunk) * 8192;
    bulk_g2s(stg + ST_AHI, (const char*)g_xhi + at, 8192, mbar);
    bulk_g2s(stg + ST_ALO, (const char*)g_xlo + at, 8192, mbar);
    bulk_g2s(stg + ST_BHI, (const char*)g_whi + bt, 8192, mbar);
    bulk_g2s(stg + ST_BLO, (const char*)g_wlo + bt, 8192, mbar);
}

__global__ __launch_bounds__(512, 1)
void sopa_gemm_mma() {
    extern __shared__ char smem[];
    const uint32_t sb = smem_to_u32(smem);
    const int tid  = threadIdx.x;
    const int lane = tid & 31;
    const int warp = tid >> 5;
    const int wm = (warp >> 2) * 32;
    const int wn = (warp & 3) * 32;

    const int nb = blockIdx.x;        // e2 block (0..15)
    const int mb = blockIdx.y;        // m block (0..255)
    const int bn = nb * 128;
    const int bm = mb * 128;

    if (tid < 128) ((float*)(smem + OFF_BIAS))[tid] = g_bias2[bn + tid];
    if (tid == 0) {
        #pragma unroll
        for (int s = 0; s < NSTAGE_; s++)
            MBARRIER_INIT(sb + OFF_MBAR + s * 8, 1);
    }
    __syncthreads();

    if (tid == 0) {
        #pragma unroll
        for (int s = 0; s < NSTAGE_ - 1; s++)
            gemm_issue_bulk(sb, s, s, mb, nb);
    }

    float acc[2][4][4];
    #pragma unroll
    for (int i = 0; i < 2; i++)
        #pragma unroll
        for (int j = 0; j < 4; j++)
            #pragma unroll
            for (int k = 0; k < 4; k++) acc[i][j][k] = 0.0f;

    const int lrow = lane & 15;
    const int lsel = lane >> 4;

    #pragma unroll
    for (int c = 0; c < NCHUNK_; c++) {
        MBARRIER_WAIT_PARITY(sb + OFF_MBAR + (c & 3) * 8, (c >> 2) & 1);
        __syncthreads();
        if (tid == 0 && c + NSTAGE_ - 1 < NCHUNK_)
            gemm_issue_bulk(sb, (c + NSTAGE_ - 1) & 3, c + NSTAGE_ - 1, mb, nb);

        const uint32_t st = sb + OFF_TILES + (c & 3) * STAGE_SZ;
        #pragma unroll
        for (int kk = 0; kk < 2; kk++) {
            const int chunk = kk * 2 + lsel;
            uint32_t aHi[2][4], aLo[2][4], bHi[2][4], bLo[2][4];
            #pragma unroll
            for (int mt = 0; mt < 2; mt++) {
                const uint32_t off = swzc(wm + mt * 16 + lrow, chunk);
                ldsm4(aHi[mt], st + ST_AHI + off);
                ldsm4(aLo[mt], st + ST_ALO + off);
            }
            #pragma unroll
            for (int ng = 0; ng < 2; ng++) {
                const uint32_t off = swzc(wn + ng * 16 + lrow, chunk);
                ldsm4(bHi[ng], st + ST_BHI + off);
                ldsm4(bLo[ng], st + ST_BLO + off);
            }
            #pragma unroll
            for (int mt = 0; mt < 2; mt++)
                #pragma unroll
                for (int nt = 0; nt < 4; nt++) {
                    const int ng = nt >> 1, sl = nt & 1;
                    mma16816(acc[mt][nt], aHi[mt], bHi[ng][sl], bHi[ng][sl + 2]);
                    mma16816(acc[mt][nt], aHi[mt], bLo[ng][sl], bLo[ng][sl + 2]);
                    mma16816(acc[mt][nt], aLo[mt], bHi[ng][sl], bHi[ng][sl + 2]);
                }
        }
    }

    // epilogue: +bias, scalar stores into the padded layout
    const float* bs = (const float*)(smem + OFF_BIAS);
    #pragma unroll
    for (int nt = 0; nt < 4; nt++) {
        const int col = wn + nt * 8 + (lane & 3) * 2;
        const int e2 = bn + col;
        const int po0 = packed_off(e2);
        const int po1 = packed_off(e2 + 1);
        const float bx = bs[col], by = bs[col + 1];
        #pragma unroll
        for (int mt = 0; mt < 2; mt++) {
            const int r0 = bm + wm + mt * 16 + (lane >> 2);
            float* d0 = g_tr + (size_t)r0 * E2P_;
            float* d1 = g_tr + (size_t)(r0 + 8) * E2P_;
            d0[po0] = acc[mt][nt][0] + bx;
            d0[po1] = acc[mt][nt][1] + by;
            d1[po0] = acc[mt][nt][2] + bx;
            d1[po1] = acc[mt][nt][3] + by;
        }
    }
}

// ===========================================================================
// Scan: thread per (b,n); templated on pattern length; 16-stage cp.async.
// (unchanged from the passing R6 version)
// ===========================================================================
#define SNS_ 16
#define SSTG_ 3072                       // 64 threads * 48 B
#define SCAN_SMEM (SNS_ * SSTG_)         // 49152

template<int PLEN, int NQ>
__device__ __forceinline__ void scan_body(int b, int n, int colpad,
                                          const int* __restrict__ input_len,
                                          const float* __restrict__ epsilon,
                                          float* __restrict__ out,
                                          char* ssm, uint32_t sb, int tidx) {
    float eps[PLEN - 1];
    #pragma unroll
    for (int i = 0; i < PLEN - 1; i++) eps[i] = epsilon[n * 5 + i];

    const int len = input_len[b];

    float h[PLEN];
    h[0] = 0.0f;
    #pragma unroll
    for (int i = 1; i < PLEN; i++) h[i] = ZERO_;
    float s = ZERO_;
    float ts = -1.0f;                   // tanhf(-100) == -1

    const float* base = g_tr + (size_t)b * E2P_ + colpad;
    float* ob = out + (size_t)b * N_ + n;
    const size_t tstride = (size_t)B_ * E2P_;
    const size_t ostride = (size_t)B_ * N_;
    const uint32_t slot = sb + tidx * 48;

    #pragma unroll
    for (int t = 0; t < SNS_ - 1; t++) {
        const float* g = base + (size_t)t * tstride;
        const uint32_t d = slot + t * SSTG_;
        #pragma unroll
        for (int q = 0; q < NQ; q++) cpa16(d + q * 16, g + q * 4);
        CP_COMMIT();
    }

    #pragma unroll 4
    for (int t = 0; t < L_; t++) {
        CP_WAIT(SNS_ - 2);
        const uint32_t doff = (uint32_t)(tidx * 48) + (t & (SNS_ - 1)) * SSTG_;
        float q[NQ * 4];
        #pragma unroll
        for (int i = 0; i < NQ; i++) {
            float4 v = *(const float4*)(ssm + doff + i * 16);
            q[i * 4 + 0] = v.x; q[i * 4 + 1] = v.y;
            q[i * 4 + 2] = v.z; q[i * 4 + 3] = v.w;
        }
        if (t + SNS_ - 1 < L_) {
            const float* g = base + (size_t)(t + SNS_ - 1) * tstride;
            const uint32_t nd = slot + ((t + SNS_ - 1) & (SNS_ - 1)) * SSTG_;
            #pragma unroll
            for (int qq = 0; qq < NQ; qq++) cpa16(nd + qq * 16, g + qq * 4);
        }
        CP_COMMIT();

        // q[0..PLEN-1] = self-loop, q[PLEN..2*PLEN-2] = advance
        float ae[PLEN];
        ae[0] = h[0];
        #pragma unroll
        for (int i = 1; i < PLEN; i++) ae[i] = fmaxf(h[i], h[i - 1] + eps[i - 1]);

        h[0] = fmaxf(0.0f, ae[0] + q[0]);
        #pragma unroll
        for (int i = 1; i < PLEN; i++)
            h[i] = fmaxf(ae[i - 1] + q[PLEN + i - 1], ae[i] + q[i]);

        float ev = h[PLEN - 1];
        if (len >= t && ev > s) {
            s = ev;
            ts = tanhf(s);
        }
        ob[(size_t)t * ostride] = ts;
    }
}

__global__ __launch_bounds__(64)
void sopa_scan(const int* __restrict__ input_len,
               const float* __restrict__ epsilon,
               float* __restrict__ out) {
    extern __shared__ char ssm[];
    const uint32_t sb = smem_to_u32(ssm);
    const int tidx = threadIdx.x;
    const int b = blockIdx.x >> 2;
    const int g = blockIdx.x & 3;
    const int n = (g << 6) | tidx;

    switch (g) {
        case 0: scan_body<3, 2>(b, n, 0    + tidx * 8,  input_len, epsilon, out, ssm, sb, tidx); break;
        case 1: scan_body<4, 2>(b, n, 512  + tidx * 8,  input_len, epsilon, out, ssm, sb, tidx); break;
        case 2: scan_body<5, 3>(b, n, 1024 + tidx * 12, input_len, epsilon, out, ssm, sb, tidx); break;
        default: scan_body<6, 3>(b, n, 1792 + tidx * 12, input_len, epsilon, out, ssm, sb, tidx); break;
    }
}

// ===========================================================================
extern "C" void kernel_launch(void* const* d_in, const int* in_sizes, int n_in,
                              void* d_out, int out_size) {
    const float* x         = (const float*)d_in[0];   // (L,B,D) f32
    const int*   input_len = (const int*)  d_in[1];   // (B,)   i32
    const float* diags     = (const float*)d_in[2];   // (E,D)  f32
    const float* bias      = (const float*)d_in[3];   // (E,1)  f32
    const float* epsilon   = (const float*)d_in[4];   // (N,P-1) f32
    float*       out       = (float*)d_out;           // (L,B,N) f32

    cudaFuncSetAttribute(sopa_gemm_mma, cudaFuncAttributeMaxDynamicSharedMemorySize,
                         SMEM_BYTES);
    cudaFuncSetAttribute(sopa_scan, cudaFuncAttributeMaxDynamicSharedMemorySize,
                         SCAN_SMEM);

    cvt_split_tiled<<<M_ * 32 / 256, 256>>>(x);       // 4096 blocks
    repack_w_tiled<<<E2_, 32>>>(diags, bias);

    dim3 ggrid(E2_ / 128, M_ / 128);   // (16, 256)
    sopa_gemm_mma<<<ggrid, 512, SMEM_BYTES>>>();
    sopa_scan<<<256, 64, SCAN_SMEM>>>(input_len, epsilon, out);
}

// round 8
// speedup vs baseline: 2.5160x; 1.0116x over previous
#include <cuda_runtime.h>
#include <cuda_fp16.h>
#include <cstdint>

// Problem constants (Sopa_18897856102689)
#define L_ 512
#define B_ 64
#define D_ 256
#define N_ 256
#define P_ 6
#define E_ 3072            // 2*N*P, uniform 12 cols per pattern
#define M_ (L_ * B_)       // 32768
#define ZERO_ (-100.0f)

// Scratch. x/W operands stored in TILE-IMAGE layout: one tile = (128 rows x
// 32 halves) = 8192 contiguous bytes, identical to the smem stage plane image.
__device__ float  g_tr[(size_t)M_ * (size_t)E_];                // 402.7 MB
__device__ __align__(128) __half g_xhi[(size_t)M_ * D_];        // 16.8 MB
__device__ __align__(128) __half g_xlo[(size_t)M_ * D_];
__device__ __align__(128) __half g_whi[(size_t)E_ * D_];        // 1.57 MB
__device__ __align__(128) __half g_wlo[(size_t)E_ * D_];

// ===========================================================================
// helpers
// ===========================================================================
__device__ __forceinline__ uint32_t smem_to_u32(const void* p) {
    uint32_t a;
    asm("{ .reg .u64 t; cvta.to.shared.u64 t, %1; cvt.u32.u64 %0, t; }"
        : "=r"(a) : "l"(p));
    return a;
}
__device__ __forceinline__ void ldsm4(uint32_t* r, uint32_t addr) {
    asm volatile("ldmatrix.sync.aligned.m8n8.x4.shared.b16 {%0,%1,%2,%3}, [%4];"
        : "=r"(r[0]), "=r"(r[1]), "=r"(r[2]), "=r"(r[3]) : "r"(addr));
}
__device__ __forceinline__ void mma16816(float* d, const uint32_t* a,
                                         uint32_t b0, uint32_t b1) {
    asm volatile(
        "mma.sync.aligned.m16n8k16.row.col.f32.f16.f16.f32 "
        "{%0,%1,%2,%3}, {%4,%5,%6,%7}, {%8,%9}, {%0,%1,%2,%3};"
        : "+f"(d[0]), "+f"(d[1]), "+f"(d[2]), "+f"(d[3])
        : "r"(a[0]), "r"(a[1]), "r"(a[2]), "r"(a[3]), "r"(b0), "r"(b1));
}
__device__ __forceinline__ uint32_t pack2(__half a, __half b) {
    __half2 t = __halves2half2(a, b);
    return *(uint32_t*)&t;
}
__device__ __forceinline__ void cpa16(uint32_t saddr, const void* gaddr) {
    asm volatile("cp.async.cg.shared.global [%0], [%1], 16;"
                 :: "r"(saddr), "l"(gaddr));
}
#define CP_COMMIT() asm volatile("cp.async.commit_group;" ::: "memory")
#define CP_WAIT(n)  asm volatile("cp.async.wait_group %0;" :: "n"(n) : "memory")

// bulk async copy global -> shared, mbarrier completion (sm_90 PTX)
__device__ __forceinline__ void bulk_g2s(uint32_t saddr, const void* gaddr,
                                         uint32_t bytes, uint32_t mbar) {
    asm volatile(
        "cp.async.bulk.shared::cluster.global.mbarrier::complete_tx::bytes "
        "[%0], [%1], %2, [%3];"
        :: "r"(saddr), "l"(gaddr), "r"(bytes), "r"(mbar) : "memory");
}
#define MBARRIER_INIT(mbar, cnt) \
    asm volatile("mbarrier.init.shared.b64 [%0], %1;" \
                 :: "r"((uint32_t)(mbar)), "r"((uint32_t)(cnt)) : "memory")
#define MBAR_EXPECT_TX(mbar, bytes) \
    asm volatile("mbarrier.arrive.expect_tx.shared.b64 _, [%0], %1;" \
                 :: "r"((uint32_t)(mbar)), "r"((uint32_t)(bytes)) : "memory")
#define MBARRIER_WAIT_PARITY(mbar, par) do {                                   \
    uint32_t _m = (uint32_t)(mbar);                                            \
    uint32_t _p = (uint32_t)(par);                                             \
    uint32_t _d;                                                               \
    asm volatile("{\n\t.reg .pred p;\n\t"                                      \
        "mbarrier.try_wait.parity.acquire.cta.shared::cta.b64 p, [%1], %2;\n\t"\
        "selp.b32 %0, 1, 0, p;\n\t}"                                           \
        : "=r"(_d) : "r"(_m), "r"(_p) : "memory");                             \
    if (!_d) {                                                                 \
        asm volatile("{\n\t.reg .pred P1;\n\t"                                 \
            "WAIT_LOOP_%=:\n\t"                                                \
            "mbarrier.try_wait.parity.acquire.cta.shared::cta.b64 P1, [%0], %1, 0x989680;\n\t" \
            "@P1 bra.uni WAIT_DONE_%=;\n\t"                                    \
            "bra.uni WAIT_LOOP_%=;\n\t"                                        \
            "WAIT_DONE_%=:\n\t}"                                               \
            :: "r"(_m), "r"(_p) : "memory");                                   \
    }                                                                          \
} while (0)

// swizzled byte offset within a 128x32-half tile image (row=64B, 16B granule)
__device__ __forceinline__ uint32_t swzc(int row, int chunk) {  // chunk 0..3
    return (uint32_t)(row * 64 + ((chunk ^ ((row >> 1) & 3)) << 4));
}

// ===========================================================================
// Convert fp32 matrix (rows x 256) -> (hi,lo) fp16 in TILE-IMAGE layout.
// grid = rows*32/256 blocks of 256 threads; thread handles 8 consecutive k.
// ===========================================================================
__global__ __launch_bounds__(256)
void cvt_split_tiled(const float* __restrict__ src,
                     __half* __restrict__ hi_out, __half* __restrict__ lo_out) {
    const int i = blockIdx.x * 256 + threadIdx.x;
    const int m  = i >> 5;
    const int kq = i & 31;
    const float4 v0 = *(const float4*)(src + (size_t)m * D_ + kq * 8);
    const float4 v1 = *(const float4*)(src + (size_t)m * D_ + kq * 8 + 4);
    __half h0 = __float2half_rn(v0.x), h1 = __float2half_rn(v0.y);
    __half h2 = __float2half_rn(v0.z), h3 = __float2half_rn(v0.w);
    __half h4 = __float2half_rn(v1.x), h5 = __float2half_rn(v1.y);
    __half h6 = __float2half_rn(v1.z), h7 = __float2half_rn(v1.w);
    uint4 hi = { pack2(h0, h1), pack2(h2, h3), pack2(h4, h5), pack2(h6, h7) };
    uint4 lo = { pack2(__float2half_rn(v0.x - __half2float(h0)),
                       __float2half_rn(v0.y - __half2float(h1))),
                 pack2(__float2half_rn(v0.z - __half2float(h2)),
                       __float2half_rn(v0.w - __half2float(h3))),
                 pack2(__float2half_rn(v1.x - __half2float(h4)),
                       __float2half_rn(v1.y - __half2float(h5))),
                 pack2(__float2half_rn(v1.z - __half2float(h6)),
                       __float2half_rn(v1.w - __half2float(h7))) };
    const size_t off = (size_t)((m >> 7) * 8 + (kq >> 2)) * 8192
                     + swzc(m & 127, kq & 3);
    *(uint4*)((char*)hi_out + off) = hi;
    *(uint4*)((char*)lo_out + off) = lo;
}

// ===========================================================================
// GEMM: C[m][e] = sum_k x[m][k]*diags[e][k] + bias[e]
// Stages via cp.async.bulk (4 x 8KB / stage, tid0, mbarrier); fp16 hi/lo,
// 3-term mma.sync; smem-staged COALESCED epilogue (float4 row segments).
// BM=128, BN=128, BK=32, 512 threads, warp grid 4x4, warp tile 32x32.
// ===========================================================================
#define NCHUNK_ 8
#define NSTAGE_ 4
#define ST_AHI 0
#define ST_ALO 8192
#define ST_BHI 16384
#define ST_BLO 24576
#define STAGE_SZ 32768
#define OFF_MBAR  512
#define OFF_TILES 1024
#define SMEM_BYTES (OFF_TILES + NSTAGE_ * STAGE_SZ)   // 132096
#define EPS_ 136   // epilogue smem row stride (floats)

__device__ __forceinline__ void gemm_issue_bulk(uint32_t sb, int slot,
                                                int chunk, int mb, int nb) {
    const uint32_t stg = sb + OFF_TILES + slot * STAGE_SZ;
    const uint32_t mbar = sb + OFF_MBAR + slot * 8;
    MBAR_EXPECT_TX(mbar, 4 * 8192);
    const size_t at = (size_t)(mb * 8 + chunk) * 8192;
    const size_t bt = (size_t)(nb * 8 + chunk) * 8192;
    bulk_g2s(stg + ST_AHI, (const char*)g_xhi + at, 8192, mbar);
    bulk_g2s(stg + ST_ALO, (const char*)g_xlo + at, 8192, mbar);
    bulk_g2s(stg + ST_BHI, (const char*)g_whi + bt, 8192, mbar);
    bulk_g2s(stg + ST_BLO, (const char*)g_wlo + bt, 8192, mbar);
}

__global__ __launch_bounds__(512, 1)
void sopa_gemm_mma(const float* __restrict__ bias) {
    extern __shared__ char smem[];
    const uint32_t sb = smem_to_u32(smem);
    const int tid  = threadIdx.x;
    const int lane = tid & 31;
    const int warp = tid >> 5;
    const int wm = (warp >> 2) * 32;
    const int wn = (warp & 3) * 32;

    const int nb = blockIdx.x;        // e block (0..23)
    const int mb = blockIdx.y;        // m block (0..255)
    const int bn = nb * 128;
    const int bm = mb * 128;

    if (tid == 0) {
        #pragma unroll
        for (int s = 0; s < NSTAGE_; s++)
            MBARRIER_INIT(sb + OFF_MBAR + s * 8, 1);
    }
    __syncthreads();

    if (tid == 0) {
        #pragma unroll
        for (int s = 0; s < NSTAGE_ - 1; s++)
            gemm_issue_bulk(sb, s, s, mb, nb);
    }

    float acc[2][4][4];
    #pragma unroll
    for (int i = 0; i < 2; i++)
        #pragma unroll
        for (int j = 0; j < 4; j++)
            #pragma unroll
            for (int k = 0; k < 4; k++) acc[i][j][k] = 0.0f;

    const int lrow = lane & 15;
    const int lsel = lane >> 4;

    #pragma unroll
    for (int c = 0; c < NCHUNK_; c++) {
        MBARRIER_WAIT_PARITY(sb + OFF_MBAR + (c & 3) * 8, (c >> 2) & 1);
        __syncthreads();
        if (tid == 0 && c + NSTAGE_ - 1 < NCHUNK_)
            gemm_issue_bulk(sb, (c + NSTAGE_ - 1) & 3, c + NSTAGE_ - 1, mb, nb);

        const uint32_t st = sb + OFF_TILES + (c & 3) * STAGE_SZ;
        #pragma unroll
        for (int kk = 0; kk < 2; kk++) {
            const int chunk = kk * 2 + lsel;
            uint32_t aHi[2][4], aLo[2][4], bHi[2][4], bLo[2][4];
            #pragma unroll
            for (int mt = 0; mt < 2; mt++) {
                const uint32_t off = swzc(wm + mt * 16 + lrow, chunk);
                ldsm4(aHi[mt], st + ST_AHI + off);
                ldsm4(aLo[mt], st + ST_ALO + off);
            }
            #pragma unroll
            for (int ng = 0; ng < 2; ng++) {
                const uint32_t off = swzc(wn + ng * 16 + lrow, chunk);
                ldsm4(bHi[ng], st + ST_BHI + off);
                ldsm4(bLo[ng], st + ST_BLO + off);
            }
            #pragma unroll
            for (int mt = 0; mt < 2; mt++)
                #pragma unroll
                for (int nt = 0; nt < 4; nt++) {
                    const int ng = nt >> 1, sl = nt & 1;
                    mma16816(acc[mt][nt], aHi[mt], bHi[ng][sl], bHi[ng][sl + 2]);
                    mma16816(acc[mt][nt], aHi[mt], bLo[ng][sl], bLo[ng][sl + 2]);
                    mma16816(acc[mt][nt], aLo[mt], bHi[ng][sl], bHi[ng][sl + 2]);
                }
        }
    }

    // ---- epilogue: acc -> padded smem -> fully coalesced float4 stores ----
    __syncthreads();    // all ldsm complete; stage smem reusable
    float* ebuf = (float*)(smem + OFF_TILES);
    #pragma unroll
    for (int mt = 0; mt < 2; mt++) {
        const int row = wm + mt * 16 + (lane >> 2);
        #pragma unroll
        for (int nt = 0; nt < 4; nt++) {
            const int col = wn + nt * 8 + (lane & 3) * 2;
            ebuf[row * EPS_ + col]           = acc[mt][nt][0];
            ebuf[row * EPS_ + col + 1]       = acc[mt][nt][1];
            ebuf[(row + 8) * EPS_ + col]     = acc[mt][nt][2];
            ebuf[(row + 8) * EPS_ + col + 1] = acc[mt][nt][3];
        }
    }
    __syncthreads();
    #pragma unroll
    for (int i = 0; i < 8; i++) {
        const int id  = tid + i * 512;      // 0..4095
        const int row = id >> 5;            // 0..127
        const int c4  = id & 31;            // float4 index in 128-col row
        float4 v = *(const float4*)&ebuf[row * EPS_ + c4 * 4];
        const float4 bb = *(const float4*)(bias + bn + c4 * 4);
        v.x += bb.x; v.y += bb.y; v.z += bb.z; v.w += bb.w;
        *(float4*)(g_tr + (size_t)(bm + row) * E_ + bn + c4 * 4) = v;
    }
}

// ===========================================================================
// Scan: thread per (b,n); templated on pattern length; 16-stage cp.async.
// Layout per (m, n): 12 floats: [0..5]=self-loop p0..5, [6..11]=advance p0..4
// ===========================================================================
#define SNS_ 16
#define SSTG_ 3072                       // 64 threads * 48 B
#define SCAN_SMEM (SNS_ * SSTG_)         // 49152

template<int PLEN, int NQ>
__device__ __forceinline__ void scan_body(int b, int n,
                                          const int* __restrict__ input_len,
                                          const float* __restrict__ epsilon,
                                          float* __restrict__ out,
                                          char* ssm, uint32_t sb, int tidx) {
    float eps[PLEN - 1];
    #pragma unroll
    for (int i = 0; i < PLEN - 1; i++) eps[i] = epsilon[n * 5 + i];

    const int len = input_len[b];

    float h[PLEN];
    h[0] = 0.0f;
    #pragma unroll
    for (int i = 1; i < PLEN; i++) h[i] = ZERO_;
    float s = ZERO_;
    float ts = -1.0f;                   // tanhf(-100) == -1

    const float* base = g_tr + (size_t)b * E_ + (size_t)n * 12;
    float* ob = out + (size_t)b * N_ + n;
    const size_t tstride = (size_t)B_ * E_;
    const size_t ostride = (size_t)B_ * N_;
    const uint32_t slot = sb + tidx * 48;

    #pragma unroll
    for (int t = 0; t < SNS_ - 1; t++) {
        const float* g = base + (size_t)t * tstride;
        const uint32_t d = slot + t * SSTG_;
        #pragma unroll
        for (int q = 0; q < NQ; q++) cpa16(d + q * 16, g + q * 4);
        CP_COMMIT();
    }

    #pragma unroll 4
    for (int t = 0; t < L_; t++) {
        CP_WAIT(SNS_ - 2);
        const uint32_t doff = (uint32_t)(tidx * 48) + (t & (SNS_ - 1)) * SSTG_;
        float q[NQ * 4];
        #pragma unroll
        for (int i = 0; i < NQ; i++) {
            float4 v = *(const float4*)(ssm + doff + i * 16);
            q[i * 4 + 0] = v.x; q[i * 4 + 1] = v.y;
            q[i * 4 + 2] = v.z; q[i * 4 + 3] = v.w;
        }
        if (t + SNS_ - 1 < L_) {
            const float* g = base + (size_t)(t + SNS_ - 1) * tstride;
            const uint32_t nd = slot + ((t + SNS_ - 1) & (SNS_ - 1)) * SSTG_;
            #pragma unroll
            for (int qq = 0; qq < NQ; qq++) cpa16(nd + qq * 16, g + qq * 4);
        }
        CP_COMMIT();

        // q[0..PLEN-1] = self-loop ; q[6 + i - 1] = advance into state i
        float ae[PLEN];
        ae[0] = h[0];
        #pragma unroll
        for (int i = 1; i < PLEN; i++) ae[i] = fmaxf(h[i], h[i - 1] + eps[i - 1]);

        h[0] = fmaxf(0.0f, ae[0] + q[0]);
        #pragma unroll
        for (int i = 1; i < PLEN; i++)
            h[i] = fmaxf(ae[i - 1] + q[5 + i], ae[i] + q[i]);

        float ev = h[PLEN - 1];
        if (len >= t && ev > s) {
            s = ev;
            ts = tanhf(s);
        }
        ob[(size_t)t * ostride] = ts;
    }
}

__global__ __launch_bounds__(64)
void sopa_scan(const int* __restrict__ input_len,
               const float* __restrict__ epsilon,
               float* __restrict__ out) {
    extern __shared__ char ssm[];
    const uint32_t sb = smem_to_u32(ssm);
    const int tidx = threadIdx.x;
    const int b = blockIdx.x >> 2;
    const int g = blockIdx.x & 3;
    const int n = (g << 6) | tidx;

    switch (g) {
        case 0: scan_body<3, 2>(b, n, input_len, epsilon, out, ssm, sb, tidx); break;
        case 1: scan_body<4, 3>(b, n, input_len, epsilon, out, ssm, sb, tidx); break;
        case 2: scan_body<5, 3>(b, n, input_len, epsilon, out, ssm, sb, tidx); break;
        default: scan_body<6, 3>(b, n, input_len, epsilon, out, ssm, sb, tidx); break;
    }
}

// ===========================================================================
extern "C" void kernel_launch(void* const* d_in, const int* in_sizes, int n_in,
                              void* d_out, int out_size) {
    const float* x         = (const float*)d_in[0];   // (L,B,D) f32
    const int*   input_len = (const int*)  d_in[1];   // (B,)   i32
    const float* diags     = (const float*)d_in[2];   // (E,D)  f32
    const float* bias      = (const float*)d_in[3];   // (E,1)  f32
    const float* epsilon   = (const float*)d_in[4];   // (N,P-1) f32
    float*       out       = (float*)d_out;           // (L,B,N) f32

    cudaFuncSetAttribute(sopa_gemm_mma, cudaFuncAttributeMaxDynamicSharedMemorySize,
                         SMEM_BYTES);
    cudaFuncSetAttribute(sopa_scan, cudaFuncAttributeMaxDynamicSharedMemorySize,
                         SCAN_SMEM);

    __half *xhi, *xlo, *whi, *wlo;
    cudaGetSymbolAddress((void**)&xhi, g_xhi);
    cudaGetSymbolAddress((void**)&xlo, g_xlo);
    cudaGetSymbolAddress((void**)&whi, g_whi);
    cudaGetSymbolAddress((void**)&wlo, g_wlo);

    cvt_split_tiled<<<M_ * 32 / 256, 256>>>(x, xhi, xlo);        // 4096 blocks
    cvt_split_tiled<<<E_ * 32 / 256, 256>>>(diags, whi, wlo);    // 384 blocks

    dim3 ggrid(E_ / 128, M_ / 128);   // (24, 256)
    sopa_gemm_mma<<<ggrid, 512, SMEM_BYTES>>>(bias);
    sopa_scan<<<256, 64, SCAN_SMEM>>>(input_len, epsilon, out);
}

// round 10
// speedup vs baseline: 3.3161x; 1.3180x over previous
#include <cuda_runtime.h>
#include <cuda_fp16.h>
#include <cstdint>

// Problem constants (Sopa_18897856102689)
#define L_ 512
#define B_ 64
#define D_ 256
#define N_ 256
#define P_ 6
#define M_ (L_ * B_)       // 32768
#define ZERO_ (-100.0f)

// Padded-packed transition columns: groups g=0..3 (plen=3..6, 64 patterns each)
// real width w = 2*plen-1 = {5,7,9,11}; padded wp = {6,8,10,12}
// E3 = 64*(6+8+10+12) = 2304 ; group bases {0, 384, 896, 1536}
#define E3_ 2304

// Scratch. x/W operands in TILE-IMAGE layout: one tile = (128 rows x 32
// halves) = 8192 contiguous bytes = one smem stage plane.
__device__ float  g_tr[(size_t)M_ * (size_t)E3_];               // 302 MB
__device__ __align__(128) __half g_xhi[(size_t)M_ * D_];        // 16.8 MB
__device__ __align__(128) __half g_xlo[(size_t)M_ * D_];
__device__ __align__(128) __half g_whi[(size_t)E3_ * D_];       // 1.18 MB
__device__ __align__(128) __half g_wlo[(size_t)E3_ * D_];
__device__ float  g_bias3[E3_];

// ===========================================================================
// helpers
// ===========================================================================
__device__ __forceinline__ uint32_t smem_to_u32(const void* p) {
    uint32_t a;
    asm("{ .reg .u64 t; cvta.to.shared.u64 t, %1; cvt.u32.u64 %0, t; }"
        : "=r"(a) : "l"(p));
    return a;
}
__device__ __forceinline__ void ldsm4(uint32_t* r, uint32_t addr) {
    asm volatile("ldmatrix.sync.aligned.m8n8.x4.shared.b16 {%0,%1,%2,%3}, [%4];"
        : "=r"(r[0]), "=r"(r[1]), "=r"(r[2]), "=r"(r[3]) : "r"(addr));
}
__device__ __forceinline__ void mma16816(float* d, const uint32_t* a,
                                         uint32_t b0, uint32_t b1) {
    asm volatile(
        "mma.sync.aligned.m16n8k16.row.col.f32.f16.f16.f32 "
        "{%0,%1,%2,%3}, {%4,%5,%6,%7}, {%8,%9}, {%0,%1,%2,%3};"
        : "+f"(d[0]), "+f"(d[1]), "+f"(d[2]), "+f"(d[3])
        : "r"(a[0]), "r"(a[1]), "r"(a[2]), "r"(a[3]), "r"(b0), "r"(b1));
}
__device__ __forceinline__ uint32_t pack2(__half a, __half b) {
    __half2 t = __halves2half2(a, b);
    return *(uint32_t*)&t;
}
__device__ __forceinline__ void cpa16(uint32_t saddr, const void* gaddr) {
    asm volatile("cp.async.cg.shared.global [%0], [%1], 16;"
                 :: "r"(saddr), "l"(gaddr));
}
__device__ __forceinline__ void cpa8(uint32_t saddr, const void* gaddr) {
    asm volatile("cp.async.ca.shared.global [%0], [%1], 8;"
                 :: "r"(saddr), "l"(gaddr));
}
#define CP_COMMIT() asm volatile("cp.async.commit_group;" ::: "memory")
#define CP_WAIT(n)  asm volatile("cp.async.wait_group %0;" :: "n"(n) : "memory")

// bulk async copy global -> shared, mbarrier completion (sm_90 PTX)
__device__ __forceinline__ void bulk_g2s(uint32_t saddr, const void* gaddr,
                                         uint32_t bytes, uint32_t mbar) {
    asm volatile(
        "cp.async.bulk.shared::cluster.global.mbarrier::complete_tx::bytes "
        "[%0], [%1], %2, [%3];"
        :: "r"(saddr), "l"(gaddr), "r"(bytes), "r"(mbar) : "memory");
}
#define MBARRIER_INIT(mbar, cnt) \
    asm volatile("mbarrier.init.shared.b64 [%0], %1;" \
                 :: "r"((uint32_t)(mbar)), "r"((uint32_t)(cnt)) : "memory")
#define MBAR_EXPECT_TX(mbar, bytes) \
    asm volatile("mbarrier.arrive.expect_tx.shared.b64 _, [%0], %1;" \
                 :: "r"((uint32_t)(mbar)), "r"((uint32_t)(bytes)) : "memory")
#define MBARRIER_WAIT_PARITY(mbar, par) do {                                   \
    uint32_t _m = (uint32_t)(mbar);                                            \
    uint32_t _p = (uint32_t)(par);                                             \
    uint32_t _d;                                                               \
    asm volatile("{\n\t.reg .pred p;\n\t"                                      \
        "mbarrier.try_wait.parity.acquire.cta.shared::cta.b64 p, [%1], %2;\n\t"\
        "selp.b32 %0, 1, 0, p;\n\t}"                                           \
        : "=r"(_d) : "r"(_m), "r"(_p) : "memory");                             \
    if (!_d) {                                                                 \
        asm volatile("{\n\t.reg .pred P1;\n\t"                                 \
            "WAIT_LOOP_%=:\n\t"                                                \
            "mbarrier.try_wait.parity.acquire.cta.shared::cta.b64 P1, [%0], %1, 0x989680;\n\t" \
            "@P1 bra.uni WAIT_DONE_%=;\n\t"                                    \
            "bra.uni WAIT_LOOP_%=;\n\t"                                        \
            "WAIT_DONE_%=:\n\t}"                                               \
            :: "r"(_m), "r"(_p) : "memory");                                   \
    }                                                                          \
} while (0)

// swizzled byte offset within a 128x32-half tile image (row=64B, 16B granule)
__device__ __forceinline__ uint32_t swzc(int row, int chunk) {  // chunk 0..3
    return (uint32_t)(row * 64 + ((chunk ^ ((row >> 1) & 3)) << 4));
}

// ===========================================================================
// Convert x: fp32 -> (hi,lo) fp16 in TILE-IMAGE layout.
// ===========================================================================
__global__ __launch_bounds__(256)
void cvt_split_tiled(const float* __restrict__ src,
                     __half* __restrict__ hi_out, __half* __restrict__ lo_out) {
    const int i = blockIdx.x * 256 + threadIdx.x;
    const int m  = i >> 5;
    const int kq = i & 31;
    const float4 v0 = *(const float4*)(src + (size_t)m * D_ + kq * 8);
    const float4 v1 = *(const float4*)(src + (size_t)m * D_ + kq * 8 + 4);
    __half h0 = __float2half_rn(v0.x), h1 = __float2half_rn(v0.y);
    __half h2 = __float2half_rn(v0.z), h3 = __float2half_rn(v0.w);
    __half h4 = __float2half_rn(v1.x), h5 = __float2half_rn(v1.y);
    __half h6 = __float2half_rn(v1.z), h7 = __float2half_rn(v1.w);
    uint4 hi = { pack2(h0, h1), pack2(h2, h3), pack2(h4, h5), pack2(h6, h7) };
    uint4 lo = { pack2(__float2half_rn(v0.x - __half2float(h0)),
                       __float2half_rn(v0.y - __half2float(h1))),
                 pack2(__float2half_rn(v0.z - __half2float(h2)),
                       __float2half_rn(v0.w - __half2float(h3))),
                 pack2(__float2half_rn(v1.x - __half2float(h4)),
                       __float2half_rn(v1.y - __half2float(h5))),
                 pack2(__float2half_rn(v1.z - __half2float(h6)),
                       __float2half_rn(v1.w - __half2float(h7))) };
    const size_t off = (size_t)((m >> 7) * 8 + (kq >> 2)) * 8192
                     + swzc(m & 127, kq & 3);
    *(uint4*)((char*)hi_out + off) = hi;
    *(uint4*)((char*)lo_out + off) = lo;
}

// ===========================================================================
// Repack W into padded-packed rows (E3) in TILE-IMAGE layout + bias gather.
// Column j within a pattern row (width wp): [self p=0..plen-1,
// advance p=0..plen-2, zero pads]. grid = E3_ blocks x 32 threads.
// ===========================================================================
__global__ __launch_bounds__(32)
void repack_w_tiled(const float* __restrict__ diags, const float* __restrict__ bias) {
    const int e3 = blockIdx.x;
    int g, base, wp;
    if (e3 < 384)       { g = 0; base = 0;    wp = 6; }
    else if (e3 < 896)  { g = 1; base = 384;  wp = 8; }
    else if (e3 < 1536) { g = 2; base = 896;  wp = 10; }
    else                { g = 3; base = 1536; wp = 12; }
    const int plen = g + 3;
    const int w = 2 * plen - 1;
    const int r0 = e3 - base;
    const int nl = r0 / wp;
    const int j = r0 - nl * wp;
    const bool real = (j < w);
    const int n = (g << 6) + nl;
    const int e_orig = n * 12 + (j < plen ? j : 6 + (j - plen));

    const int t = threadIdx.x;                      // 0..31 (8-half chunks)
    uint4 hi = {0, 0, 0, 0}, lo = {0, 0, 0, 0};
    if (real) {
        const float4 v0 = *(const float4*)(diags + (size_t)e_orig * D_ + t * 8);
        const float4 v1 = *(const float4*)(diags + (size_t)e_orig * D_ + t * 8 + 4);
        __half h0 = __float2half_rn(v0.x), h1 = __float2half_rn(v0.y);
        __half h2 = __float2half_rn(v0.z), h3 = __float2half_rn(v0.w);
        __half h4 = __float2half_rn(v1.x), h5 = __float2half_rn(v1.y);
        __half h6 = __float2half_rn(v1.z), h7 = __float2half_rn(v1.w);
        hi = make_uint4(pack2(h0, h1), pack2(h2, h3), pack2(h4, h5), pack2(h6, h7));
        lo = make_uint4(pack2(__float2half_rn(v0.x - __half2float(h0)),
                              __float2half_rn(v0.y - __half2float(h1))),
                        pack2(__float2half_rn(v0.z - __half2float(h2)),
                              __float2half_rn(v0.w - __half2float(h3))),
                        pack2(__float2half_rn(v1.x - __half2float(h4)),
                              __float2half_rn(v1.y - __half2float(h5))),
                        pack2(__float2half_rn(v1.z - __half2float(h6)),
                              __float2half_rn(v1.w - __half2float(h7))));
    }
    const size_t off = (size_t)((e3 >> 7) * 8 + (t >> 2)) * 8192
                     + swzc(e3 & 127, t & 3);
    *(uint4*)((char*)g_whi + off) = hi;
    *(uint4*)((char*)g_wlo + off) = lo;
    if (t == 0) g_bias3[e3] = real ? bias[e_orig] : 0.0f;
}

// ===========================================================================
// GEMM: C[m][e3] = sum_k x[m][k]*Wpad[e3][k] + bias3[e3]
// cp.async.bulk staging; fp16 hi/lo 3-term mma.sync; coalesced smem epilogue.
// BM=128, BN=128, BK=32, 512 threads, warp grid 4x4, warp tile 32x32.
// ===========================================================================
#define NCHUNK_ 8
#define NSTAGE_ 4
#define ST_AHI 0
#define ST_ALO 8192
#define ST_BHI 16384
#define ST_BLO 24576
#define STAGE_SZ 32768
#define OFF_MBAR  512
#define OFF_TILES 1024
#define SMEM_BYTES (OFF_TILES + NSTAGE_ * STAGE_SZ)   // 132096
#define EPS_ 136   // epilogue smem row stride (floats)

__device__ __forceinline__ void gemm_issue_bulk(uint32_t sb, int slot,
                                                int chunk, int mb, int nb) {
    const uint32_t stg = sb + OFF_TILES + slot * STAGE_SZ;
    const uint32_t mbar = sb + OFF_MBAR + slot * 8;
    MBAR_EXPECT_TX(mbar, 4 * 8192);
    const size_t at = (size_t)(mb * 8 + chunk) * 8192;
    const size_t bt = (size_t)(nb * 8 + chunk) * 8192;
    bulk_g2s(stg + ST_AHI, (const char*)g_xhi + at, 8192, mbar);
    bulk_g2s(stg + ST_ALO, (const char*)g_xlo + at, 8192, mbar);
    bulk_g2s(stg + ST_BHI, (const char*)g_whi + bt, 8192, mbar);
    bulk_g2s(stg + ST_BLO, (const char*)g_wlo + bt, 8192, mbar);
}

__global__ __launch_bounds__(512, 1)
void sopa_gemm_mma() {
    extern __shared__ char smem[];
    const uint32_t sb = smem_to_u32(smem);
    const int tid  = threadIdx.x;
    const int lane = tid & 31;
    const int warp = tid >> 5;
    const int wm = (warp >> 2) * 32;
    const int wn = (warp & 3) * 32;

    const int nb = blockIdx.x;        // e3 block (0..17)
    const int mb = blockIdx.y;        // m block (0..255)
    const int bn = nb * 128;
    const int bm = mb * 128;

    if (tid == 0) {
        #pragma unroll
        for (int s = 0; s < NSTAGE_; s++)
            MBARRIER_INIT(sb + OFF_MBAR + s * 8, 1);
    }
    __syncthreads();

    if (tid == 0) {
        #pragma unroll
        for (int s = 0; s < NSTAGE_ - 1; s++)
            gemm_issue_bulk(sb, s, s, mb, nb);
    }

    float acc[2][4][4];
    #pragma unroll
    for (int i = 0; i < 2; i++)
        #pragma unroll
        for (int j = 0; j < 4; j++)
            #pragma unroll
            for (int k = 0; k < 4; k++) acc[i][j][k] = 0.0f;

    const int lrow = lane & 15;
    const int lsel = lane >> 4;

    #pragma unroll
    for (int c = 0; c < NCHUNK_; c++) {
        MBARRIER_WAIT_PARITY(sb + OFF_MBAR + (c & 3) * 8, (c >> 2) & 1);
        __syncthreads();
        if (tid == 0 && c + NSTAGE_ - 1 < NCHUNK_)
            gemm_issue_bulk(sb, (c + NSTAGE_ - 1) & 3, c + NSTAGE_ - 1, mb, nb);

        const uint32_t st = sb + OFF_TILES + (c & 3) * STAGE_SZ;
        #pragma unroll
        for (int kk = 0; kk < 2; kk++) {
            const int chunk = kk * 2 + lsel;
            uint32_t aHi[2][4], aLo[2][4], bHi[2][4], bLo[2][4];
            #pragma unroll
            for (int mt = 0; mt < 2; mt++) {
                const uint32_t off = swzc(wm + mt * 16 + lrow, chunk);
                ldsm4(aHi[mt], st + ST_AHI + off);
                ldsm4(aLo[mt], st + ST_ALO + off);
            }
            #pragma unroll
            for (int ng = 0; ng < 2; ng++) {
                const uint32_t off = swzc(wn + ng * 16 + lrow, chunk);
                ldsm4(bHi[ng], st + ST_BHI + off);
                ldsm4(bLo[ng], st + ST_BLO + off);
            }
            #pragma unroll
            for (int mt = 0; mt < 2; mt++)
                #pragma unroll
                for (int nt = 0; nt < 4; nt++) {
                    const int ng = nt >> 1, sl = nt & 1;
                    mma16816(acc[mt][nt], aHi[mt], bHi[ng][sl], bHi[ng][sl + 2]);
                    mma16816(acc[mt][nt], aHi[mt], bLo[ng][sl], bLo[ng][sl + 2]);
                    mma16816(acc[mt][nt], aLo[mt], bHi[ng][sl], bHi[ng][sl + 2]);
                }
        }
    }

    // ---- epilogue: acc -> padded smem -> fully coalesced float4 stores ----
    __syncthreads();
    float* ebuf = (float*)(smem + OFF_TILES);
    #pragma unroll
    for (int mt = 0; mt < 2; mt++) {
        const int row = wm + mt * 16 + (lane >> 2);
        #pragma unroll
        for (int nt = 0; nt < 4; nt++) {
            const int col = wn + nt * 8 + (lane & 3) * 2;
            ebuf[row * EPS_ + col]           = acc[mt][nt][0];
            ebuf[row * EPS_ + col + 1]       = acc[mt][nt][1];
            ebuf[(row + 8) * EPS_ + col]     = acc[mt][nt][2];
            ebuf[(row + 8) * EPS_ + col + 1] = acc[mt][nt][3];
        }
    }
    __syncthreads();
    #pragma unroll
    for (int i = 0; i < 8; i++) {
        const int id  = tid + i * 512;      // 0..4095
        const int row = id >> 5;            // 0..127
        const int c4  = id & 31;            // float4 index in 128-col row
        float4 v = *(const float4*)&ebuf[row * EPS_ + c4 * 4];
        const float4 bb = *(const float4*)(g_bias3 + bn + c4 * 4);
        v.x += bb.x; v.y += bb.y; v.z += bb.z; v.w += bb.w;
        *(float4*)(g_tr + (size_t)(bm + row) * E3_ + bn + c4 * 4) = v;
    }
}

// ===========================================================================
// Scan: thread per (b,n); templated on (PLEN, WPF); 16-stage cp.async.
// Row layout (WPF floats): [0..PLEN-1]=self, [PLEN..2PLEN-2]=advance, pads.
// ===========================================================================
#define SNS_ 16
#define SSTG_ 3072                       // 64 threads * 48 B
#define SCAN_SMEM (SNS_ * SSTG_)         // 49152

template<int PLEN, int WPF>
__device__ __forceinline__ void scan_body(int b, int n, int colbase,
                                          const int* __restrict__ input_len,
                                          const float* __restrict__ epsilon,
                                          float* __restrict__ out,
                                          char* ssm, uint32_t sb, int tidx) {
    float eps[PLEN - 1];
    #pragma unroll
    for (int i = 0; i < PLEN - 1; i++) eps[i] = epsilon[n * 5 + i];

    const int len = input_len[b];

    float h[PLEN];
    h[0] = 0.0f;
    #pragma unroll
    for (int i = 1; i < PLEN; i++) h[i] = ZERO_;
    float s = ZERO_;
    float ts = -1.0f;                   // tanhf(-100) == -1

    const float* base = g_tr + (size_t)b * E3_ + colbase;
    float* ob = out + (size_t)b * N_ + n;
    const size_t tstride = (size_t)B_ * E3_;
    const size_t ostride = (size_t)B_ * N_;
    const uint32_t slot = sb + tidx * 48;

    #pragma unroll
    for (int t = 0; t < SNS_ - 1; t++) {
        const float* g = base + (size_t)t * tstride;
        const uint32_t d = slot + t * SSTG_;
        if constexpr (WPF % 4 == 0) {
            #pragma unroll
            for (int q = 0; q < WPF / 4; q++) cpa16(d + q * 16, g + q * 4);
        } else {
            #pragma unroll
            for (int q = 0; q < WPF / 2; q++) cpa8(d + q * 8, g + q * 2);
        }
        CP_COMMIT();
    }

    #pragma unroll 4
    for (int t = 0; t < L_; t++) {
        CP_WAIT(SNS_ - 2);
        const uint32_t doff = (uint32_t)(tidx * 48) + (t & (SNS_ - 1)) * SSTG_;
        float q[2 * PLEN - 1];
        #pragma unroll
        for (int i = 0; i < 2 * PLEN - 1; i++)
            q[i] = *(const float*)(ssm + doff + i * 4);
        if (t + SNS_ - 1 < L_) {
            const float* g = base + (size_t)(t + SNS_ - 1) * tstride;
            const uint32_t nd = slot + ((t + SNS_ - 1) & (SNS_ - 1)) * SSTG_;
            if constexpr (WPF % 4 == 0) {
                #pragma unroll
                for (int qq = 0; qq < WPF / 4; qq++) cpa16(nd + qq * 16, g + qq * 4);
            } else {
                #pragma unroll
                for (int qq = 0; qq < WPF / 2; qq++) cpa8(nd + qq * 8, g + qq * 2);
            }
        }
        CP_COMMIT();

        float ae[PLEN];
        ae[0] = h[0];
        #pragma unroll
        for (int i = 1; i < PLEN; i++) ae[i] = fmaxf(h[i], h[i - 1] + eps[i - 1]);

        h[0] = fmaxf(0.0f, ae[0] + q[0]);
        #pragma unroll
        for (int i = 1; i < PLEN; i++)
            h[i] = fmaxf(ae[i - 1] + q[PLEN + i - 1], ae[i] + q[i]);

        float ev = h[PLEN - 1];
        if (len >= t && ev > s) {
            s = ev;
            ts = tanhf(s);
        }
        ob[(size_t)t * ostride] = ts;
    }
}

__global__ __launch_bounds__(64)
void sopa_scan(const int* __restrict__ input_len,
               const float* __restrict__ epsilon,
               float* __restrict__ out) {
    extern __shared__ char ssm[];
    const uint32_t sb = smem_to_u32(ssm);
    const int tidx = threadIdx.x;
    const int b = blockIdx.x >> 2;
    const int g = blockIdx.x & 3;
    const int n = (g << 6) | tidx;

    switch (g) {
        case 0: scan_body<3, 6>(b, n, 0    + tidx * 6,  input_len, epsilon, out, ssm, sb, tidx); break;
        case 1: scan_body<4, 8>(b, n, 384  + tidx * 8,  input_len, epsilon, out, ssm, sb, tidx); break;
        case 2: scan_body<5, 10>(b, n, 896  + tidx * 10, input_len, epsilon, out, ssm, sb, tidx); break;
        default: scan_body<6, 12>(b, n, 1536 + tidx * 12, input_len, epsilon, out, ssm, sb, tidx); break;
    }
}

// ===========================================================================
extern "C" void kernel_launch(void* const* d_in, const int* in_sizes, int n_in,
                              void* d_out, int out_size) {
    const float* x         = (const float*)d_in[0];   // (L,B,D) f32
    const int*   input_len = (const int*)  d_in[1];   // (B,)   i32
    const float* diags     = (const float*)d_in[2];   // (E,D)  f32
    const float* bias      = (const float*)d_in[3];   // (E,1)  f32
    const float* epsilon   = (const float*)d_in[4];   // (N,P-1) f32
    float*       out       = (float*)d_out;           // (L,B,N) f32

    cudaFuncSetAttribute(sopa_gemm_mma, cudaFuncAttributeMaxDynamicSharedMemorySize,
                         SMEM_BYTES);
    cudaFuncSetAttribute(sopa_scan, cudaFuncAttributeMaxDynamicSharedMemorySize,
                         SCAN_SMEM);

    __half *xhi, *xlo;
    cudaGetSymbolAddress((void**)&xhi, g_xhi);
    cudaGetSymbolAddress((void**)&xlo, g_xlo);

    cvt_split_tiled<<<M_ * 32 / 256, 256>>>(x, xhi, xlo);   // 4096 blocks
    repack_w_tiled<<<E3_, 32>>>(diags, bias);

    dim3 ggrid(E3_ / 128, M_ / 128);   // (18, 256)
    sopa_gemm_mma<<<ggrid, 512, SMEM_BYTES>>>();
    sopa_scan<<<256, 64, SCAN_SMEM>>>(input_len, epsilon, out);
}

// round 11
// speedup vs baseline: 3.3443x; 1.0085x over previous
#include <cuda_runtime.h>
#include <cuda_fp16.h>
#include <cstdint>

// Problem constants (Sopa_18897856102689)
#define L_ 512
#define B_ 64
#define D_ 256
#define N_ 256
#define P_ 6
#define M_ (L_ * B_)       // 32768
#define ZERO_ (-100.0f)

// Padded-packed transition columns: groups g=0..3 (plen=3..6, 64 patterns each)
// real width w = 2*plen-1 = {5,7,9,11}; padded wp = {6,8,10,12}
// E3 = 64*(6+8+10+12) = 2304 ; group bases {0, 384, 896, 1536}
#define E3_ 2304

// Scratch. x/W operands in TILE-IMAGE layout: one tile = (128 rows x 32
// halves) = 8192 contiguous bytes = one smem stage plane.
__device__ float  g_tr[(size_t)M_ * (size_t)E3_];               // 302 MB
__device__ __align__(128) __half g_xhi[(size_t)M_ * D_];        // 16.8 MB
__device__ __align__(128) __half g_xlo[(size_t)M_ * D_];
__device__ __align__(128) __half g_whi[(size_t)E3_ * D_];       // 1.18 MB
__device__ __align__(128) __half g_wlo[(size_t)E3_ * D_];
__device__ float  g_bias3[E3_];

// ===========================================================================
// helpers
// ===========================================================================
__device__ __forceinline__ uint32_t smem_to_u32(const void* p) {
    uint32_t a;
    asm("{ .reg .u64 t; cvta.to.shared.u64 t, %1; cvt.u32.u64 %0, t; }"
        : "=r"(a) : "l"(p));
    return a;
}
__device__ __forceinline__ void ldsm4(uint32_t* r, uint32_t addr) {
    asm volatile("ldmatrix.sync.aligned.m8n8.x4.shared.b16 {%0,%1,%2,%3}, [%4];"
        : "=r"(r[0]), "=r"(r[1]), "=r"(r[2]), "=r"(r[3]) : "r"(addr));
}
__device__ __forceinline__ void mma16816(float* d, const uint32_t* a,
                                         uint32_t b0, uint32_t b1) {
    asm volatile(
        "mma.sync.aligned.m16n8k16.row.col.f32.f16.f16.f32 "
        "{%0,%1,%2,%3}, {%4,%5,%6,%7}, {%8,%9}, {%0,%1,%2,%3};"
        : "+f"(d[0]), "+f"(d[1]), "+f"(d[2]), "+f"(d[3])
        : "r"(a[0]), "r"(a[1]), "r"(a[2]), "r"(a[3]), "r"(b0), "r"(b1));
}
__device__ __forceinline__ uint32_t pack2(__half a, __half b) {
    __half2 t = __halves2half2(a, b);
    return *(uint32_t*)&t;
}
__device__ __forceinline__ void cpa16(uint32_t saddr, const void* gaddr) {
    asm volatile("cp.async.cg.shared.global [%0], [%1], 16;"
                 :: "r"(saddr), "l"(gaddr));
}
__device__ __forceinline__ void cpa8(uint32_t saddr, const void* gaddr) {
    asm volatile("cp.async.ca.shared.global [%0], [%1], 8;"
                 :: "r"(saddr), "l"(gaddr));
}
#define CP_COMMIT() asm volatile("cp.async.commit_group;" ::: "memory")
#define CP_WAIT(n)  asm volatile("cp.async.wait_group %0;" :: "n"(n) : "memory")

// bulk async copy global -> shared, mbarrier completion (sm_90 PTX)
__device__ __forceinline__ void bulk_g2s(uint32_t saddr, const void* gaddr,
                                         uint32_t bytes, uint32_t mbar) {
    asm volatile(
        "cp.async.bulk.shared::cluster.global.mbarrier::complete_tx::bytes "
        "[%0], [%1], %2, [%3];"
        :: "r"(saddr), "l"(gaddr), "r"(bytes), "r"(mbar) : "memory");
}
#define MBARRIER_INIT(mbar, cnt) \
    asm volatile("mbarrier.init.shared.b64 [%0], %1;" \
                 :: "r"((uint32_t)(mbar)), "r"((uint32_t)(cnt)) : "memory")
#define MBAR_EXPECT_TX(mbar, bytes) \
    asm volatile("mbarrier.arrive.expect_tx.shared.b64 _, [%0], %1;" \
                 :: "r"((uint32_t)(mbar)), "r"((uint32_t)(bytes)) : "memory")
#define MBARRIER_WAIT_PARITY(mbar, par) do {                                   \
    uint32_t _m = (uint32_t)(mbar);                                            \
    uint32_t _p = (uint32_t)(par);                                             \
    uint32_t _d;                                                               \
    asm volatile("{\n\t.reg .pred p;\n\t"                                      \
        "mbarrier.try_wait.parity.acquire.cta.shared::cta.b64 p, [%1], %2;\n\t"\
        "selp.b32 %0, 1, 0, p;\n\t}"                                           \
        : "=r"(_d) : "r"(_m), "r"(_p) : "memory");                             \
    if (!_d) {                                                                 \
        asm volatile("{\n\t.reg .pred P1;\n\t"                                 \
            "WAIT_LOOP_%=:\n\t"                                                \
            "mbarrier.try_wait.parity.acquire.cta.shared::cta.b64 P1, [%0], %1, 0x989680;\n\t" \
            "@P1 bra.uni WAIT_DONE_%=;\n\t"                                    \
            "bra.uni WAIT_LOOP_%=;\n\t"                                        \
            "WAIT_DONE_%=:\n\t}"                                               \
            :: "r"(_m), "r"(_p) : "memory");                                   \
    }                                                                          \
} while (0)

// swizzled byte offset within a 128x32-half tile image (row=64B, 16B granule)
__device__ __forceinline__ uint32_t swzc(int row, int chunk) {  // chunk 0..3
    return (uint32_t)(row * 64 + ((chunk ^ ((row >> 1) & 3)) << 4));
}

// ===========================================================================
// Convert x: fp32 -> (hi,lo) fp16 in TILE-IMAGE layout.
// ===========================================================================
__global__ __launch_bounds__(256)
void cvt_split_tiled(const float* __restrict__ src,
                     __half* __restrict__ hi_out, __half* __restrict__ lo_out) {
    const int i = blockIdx.x * 256 + threadIdx.x;
    const int m  = i >> 5;
    const int kq = i & 31;
    const float4 v0 = *(const float4*)(src + (size_t)m * D_ + kq * 8);
    const float4 v1 = *(const float4*)(src + (size_t)m * D_ + kq * 8 + 4);
    __half h0 = __float2half_rn(v0.x), h1 = __float2half_rn(v0.y);
    __half h2 = __float2half_rn(v0.z), h3 = __float2half_rn(v0.w);
    __half h4 = __float2half_rn(v1.x), h5 = __float2half_rn(v1.y);
    __half h6 = __float2half_rn(v1.z), h7 = __float2half_rn(v1.w);
    uint4 hi = { pack2(h0, h1), pack2(h2, h3), pack2(h4, h5), pack2(h6, h7) };
    uint4 lo = { pack2(__float2half_rn(v0.x - __half2float(h0)),
                       __float2half_rn(v0.y - __half2float(h1))),
                 pack2(__float2half_rn(v0.z - __half2float(h2)),
                       __float2half_rn(v0.w - __half2float(h3))),
                 pack2(__float2half_rn(v1.x - __half2float(h4)),
                       __float2half_rn(v1.y - __half2float(h5))),
                 pack2(__float2half_rn(v1.z - __half2float(h6)),
                       __float2half_rn(v1.w - __half2float(h7))) };
    const size_t off = (size_t)((m >> 7) * 8 + (kq >> 2)) * 8192
                     + swzc(m & 127, kq & 3);
    *(uint4*)((char*)hi_out + off) = hi;
    *(uint4*)((char*)lo_out + off) = lo;
}

// ===========================================================================
// Repack W into padded-packed rows (E3) in TILE-IMAGE layout + bias gather.
// Column j within a pattern row (width wp): [self p=0..plen-1,
// advance p=0..plen-2, zero pads]. grid = E3_ blocks x 32 threads.
// ===========================================================================
__global__ __launch_bounds__(32)
void repack_w_tiled(const float* __restrict__ diags, const float* __restrict__ bias) {
    const int e3 = blockIdx.x;
    int g, base, wp;
    if (e3 < 384)       { g = 0; base = 0;    wp = 6; }
    else if (e3 < 896)  { g = 1; base = 384;  wp = 8; }
    else if (e3 < 1536) { g = 2; base = 896;  wp = 10; }
    else                { g = 3; base = 1536; wp = 12; }
    const int plen = g + 3;
    const int w = 2 * plen - 1;
    const int r0 = e3 - base;
    const int nl = r0 / wp;
    const int j = r0 - nl * wp;
    const bool real = (j < w);
    const int n = (g << 6) + nl;
    const int e_orig = n * 12 + (j < plen ? j : 6 + (j - plen));

    const int t = threadIdx.x;                      // 0..31 (8-half chunks)
    uint4 hi = {0, 0, 0, 0}, lo = {0, 0, 0, 0};
    if (real) {
        const float4 v0 = *(const float4*)(diags + (size_t)e_orig * D_ + t * 8);
        const float4 v1 = *(const float4*)(diags + (size_t)e_orig * D_ + t * 8 + 4);
        __half h0 = __float2half_rn(v0.x), h1 = __float2half_rn(v0.y);
        __half h2 = __float2half_rn(v0.z), h3 = __float2half_rn(v0.w);
        __half h4 = __float2half_rn(v1.x), h5 = __float2half_rn(v1.y);
        __half h6 = __float2half_rn(v1.z), h7 = __float2half_rn(v1.w);
        hi = make_uint4(pack2(h0, h1), pack2(h2, h3), pack2(h4, h5), pack2(h6, h7));
        lo = make_uint4(pack2(__float2half_rn(v0.x - __half2float(h0)),
                              __float2half_rn(v0.y - __half2float(h1))),
                        pack2(__float2half_rn(v0.z - __half2float(h2)),
                              __float2half_rn(v0.w - __half2float(h3))),
                        pack2(__float2half_rn(v1.x - __half2float(h4)),
                              __float2half_rn(v1.y - __half2float(h5))),
                        pack2(__float2half_rn(v1.z - __half2float(h6)),
                              __float2half_rn(v1.w - __half2float(h7))));
    }
    const size_t off = (size_t)((e3 >> 7) * 8 + (t >> 2)) * 8192
                     + swzc(e3 & 127, t & 3);
    *(uint4*)((char*)g_whi + off) = hi;
    *(uint4*)((char*)g_wlo + off) = lo;
    if (t == 0) g_bias3[e3] = real ? bias[e_orig] : 0.0f;
}

// ===========================================================================
// GEMM: C[m][e3] = sum_k x[m][k]*Wpad[e3][k] + bias3[e3]
// cp.async.bulk staging; fp16 hi/lo 3-term mma.sync; coalesced smem epilogue.
// BM=128, BN=128, BK=32, 512 threads, warp grid 4x4, warp tile 32x32.
// (unchanged from passing R10 version — at the legacy-HMMA floor)
// ===========================================================================
#define NCHUNK_ 8
#define NSTAGE_ 4
#define ST_AHI 0
#define ST_ALO 8192
#define ST_BHI 16384
#define ST_BLO 24576
#define STAGE_SZ 32768
#define OFF_MBAR  512
#define OFF_TILES 1024
#define SMEM_BYTES (OFF_TILES + NSTAGE_ * STAGE_SZ)   // 132096
#define EPS_ 136   // epilogue smem row stride (floats)

__device__ __forceinline__ void gemm_issue_bulk(uint32_t sb, int slot,
                                                int chunk, int mb, int nb) {
    const uint32_t stg = sb + OFF_TILES + slot * STAGE_SZ;
    const uint32_t mbar = sb + OFF_MBAR + slot * 8;
    MBAR_EXPECT_TX(mbar, 4 * 8192);
    const size_t at = (size_t)(mb * 8 + chunk) * 8192;
    const size_t bt = (size_t)(nb * 8 + chunk) * 8192;
    bulk_g2s(stg + ST_AHI, (const char*)g_xhi + at, 8192, mbar);
    bulk_g2s(stg + ST_ALO, (const char*)g_xlo + at, 8192, mbar);
    bulk_g2s(stg + ST_BHI, (const char*)g_whi + bt, 8192, mbar);
    bulk_g2s(stg + ST_BLO, (const char*)g_wlo + bt, 8192, mbar);
}

__global__ __launch_bounds__(512, 1)
void sopa_gemm_mma() {
    extern __shared__ char smem[];
    const uint32_t sb = smem_to_u32(smem);
    const int tid  = threadIdx.x;
    const int lane = tid & 31;
    const int warp = tid >> 5;
    const int wm = (warp >> 2) * 32;
    const int wn = (warp & 3) * 32;

    const int nb = blockIdx.x;        // e3 block (0..17)
    const int mb = blockIdx.y;        // m block (0..255)
    const int bn = nb * 128;
    const int bm = mb * 128;

    if (tid == 0) {
        #pragma unroll
        for (int s = 0; s < NSTAGE_; s++)
            MBARRIER_INIT(sb + OFF_MBAR + s * 8, 1);
    }
    __syncthreads();

    if (tid == 0) {
        #pragma unroll
        for (int s = 0; s < NSTAGE_ - 1; s++)
            gemm_issue_bulk(sb, s, s, mb, nb);
    }

    float acc[2][4][4];
    #pragma unroll
    for (int i = 0; i < 2; i++)
        #pragma unroll
        for (int j = 0; j < 4; j++)
            #pragma unroll
            for (int k = 0; k < 4; k++) acc[i][j][k] = 0.0f;

    const int lrow = lane & 15;
    const int lsel = lane >> 4;

    #pragma unroll
    for (int c = 0; c < NCHUNK_; c++) {
        MBARRIER_WAIT_PARITY(sb + OFF_MBAR + (c & 3) * 8, (c >> 2) & 1);
        __syncthreads();
        if (tid == 0 && c + NSTAGE_ - 1 < NCHUNK_)
            gemm_issue_bulk(sb, (c + NSTAGE_ - 1) & 3, c + NSTAGE_ - 1, mb, nb);

        const uint32_t st = sb + OFF_TILES + (c & 3) * STAGE_SZ;
        #pragma unroll
        for (int kk = 0; kk < 2; kk++) {
            const int chunk = kk * 2 + lsel;
            uint32_t aHi[2][4], aLo[2][4], bHi[2][4], bLo[2][4];
            #pragma unroll
            for (int mt = 0; mt < 2; mt++) {
                const uint32_t off = swzc(wm + mt * 16 + lrow, chunk);
                ldsm4(aHi[mt], st + ST_AHI + off);
                ldsm4(aLo[mt], st + ST_ALO + off);
            }
            #pragma unroll
            for (int ng = 0; ng < 2; ng++) {
                const uint32_t off = swzc(wn + ng * 16 + lrow, chunk);
                ldsm4(bHi[ng], st + ST_BHI + off);
                ldsm4(bLo[ng], st + ST_BLO + off);
            }
            #pragma unroll
            for (int mt = 0; mt < 2; mt++)
                #pragma unroll
                for (int nt = 0; nt < 4; nt++) {
                    const int ng = nt >> 1, sl = nt & 1;
                    mma16816(acc[mt][nt], aHi[mt], bHi[ng][sl], bHi[ng][sl + 2]);
                    mma16816(acc[mt][nt], aHi[mt], bLo[ng][sl], bLo[ng][sl + 2]);
                    mma16816(acc[mt][nt], aLo[mt], bHi[ng][sl], bHi[ng][sl + 2]);
                }
        }
    }

    // ---- epilogue: acc -> padded smem -> fully coalesced float4 stores ----
    __syncthreads();
    float* ebuf = (float*)(smem + OFF_TILES);
    #pragma unroll
    for (int mt = 0; mt < 2; mt++) {
        const int row = wm + mt * 16 + (lane >> 2);
        #pragma unroll
        for (int nt = 0; nt < 4; nt++) {
            const int col = wn + nt * 8 + (lane & 3) * 2;
            ebuf[row * EPS_ + col]           = acc[mt][nt][0];
            ebuf[row * EPS_ + col + 1]       = acc[mt][nt][1];
            ebuf[(row + 8) * EPS_ + col]     = acc[mt][nt][2];
            ebuf[(row + 8) * EPS_ + col + 1] = acc[mt][nt][3];
        }
    }
    __syncthreads();
    #pragma unroll
    for (int i = 0; i < 8; i++) {
        const int id  = tid + i * 512;      // 0..4095
        const int row = id >> 5;            // 0..127
        const int c4  = id & 31;            // float4 index in 128-col row
        float4 v = *(const float4*)&ebuf[row * EPS_ + c4 * 4];
        const float4 bb = *(const float4*)(g_bias3 + bn + c4 * 4);
        v.x += bb.x; v.y += bb.y; v.z += bb.z; v.w += bb.w;
        *(float4*)(g_tr + (size_t)(bm + row) * E3_ + bn + c4 * 4) = v;
    }
}

// ===========================================================================
// Scan v3: 128 blocks x 128 threads (SINGLE wave on 148 SMs).
// block = (b, half): half 0 -> groups 0,1 (n 0..127); half 1 -> groups 2,3.
// Each warp uniform PLEN. 48B slot per thread, 16-stage cp.async pipeline.
// ===========================================================================
#define SNS_ 16
#define SSTG_ 6144                       // 128 threads * 48 B
#define SCAN_SMEM (SNS_ * SSTG_)         // 98304

template<int PLEN, int WPF>
__device__ __forceinline__ void scan_body(int b, int n, int colbase,
                                          const int* __restrict__ input_len,
                                          const float* __restrict__ epsilon,
                                          float* __restrict__ out,
                                          char* ssm, uint32_t sb, int tidx) {
    float eps[PLEN - 1];
    #pragma unroll
    for (int i = 0; i < PLEN - 1; i++) eps[i] = epsilon[n * 5 + i];

    const int len = input_len[b];

    float h[PLEN];
    h[0] = 0.0f;
    #pragma unroll
    for (int i = 1; i < PLEN; i++) h[i] = ZERO_;
    float s = ZERO_;
    float ts = -1.0f;                   // tanhf(-100) == -1

    const float* base = g_tr + (size_t)b * E3_ + colbase;
    float* ob = out + (size_t)b * N_ + n;
    const size_t tstride = (size_t)B_ * E3_;
    const size_t ostride = (size_t)B_ * N_;
    const uint32_t slot = sb + tidx * 48;

    #pragma unroll
    for (int t = 0; t < SNS_ - 1; t++) {
        const float* g = base + (size_t)t * tstride;
        const uint32_t d = slot + t * SSTG_;
        if constexpr (WPF % 4 == 0) {
            #pragma unroll
            for (int q = 0; q < WPF / 4; q++) cpa16(d + q * 16, g + q * 4);
        } else {
            #pragma unroll
            for (int q = 0; q < WPF / 2; q++) cpa8(d + q * 8, g + q * 2);
        }
        CP_COMMIT();
    }

    #pragma unroll 4
    for (int t = 0; t < L_; t++) {
        CP_WAIT(SNS_ - 2);
        const uint32_t doff = (uint32_t)(tidx * 48) + (t & (SNS_ - 1)) * SSTG_;
        float q[2 * PLEN - 1];
        #pragma unroll
        for (int i = 0; i < 2 * PLEN - 1; i++)
            q[i] = *(const float*)(ssm + doff + i * 4);
        if (t + SNS_ - 1 < L_) {
            const float* g = base + (size_t)(t + SNS_ - 1) * tstride;
            const uint32_t nd = slot + ((t + SNS_ - 1) & (SNS_ - 1)) * SSTG_;
            if constexpr (WPF % 4 == 0) {
                #pragma unroll
                for (int qq = 0; qq < WPF / 4; qq++) cpa16(nd + qq * 16, g + qq * 4);
            } else {
                #pragma unroll
                for (int qq = 0; qq < WPF / 2; qq++) cpa8(nd + qq * 8, g + qq * 2);
            }
        }
        CP_COMMIT();

        float ae[PLEN];
        ae[0] = h[0];
        #pragma unroll
        for (int i = 1; i < PLEN; i++) ae[i] = fmaxf(h[i], h[i - 1] + eps[i - 1]);

        h[0] = fmaxf(0.0f, ae[0] + q[0]);
        #pragma unroll
        for (int i = 1; i < PLEN; i++)
            h[i] = fmaxf(ae[i - 1] + q[PLEN + i - 1], ae[i] + q[i]);

        float ev = h[PLEN - 1];
        if (len >= t && ev > s) {
            s = ev;
            ts = tanhf(s);
        }
        ob[(size_t)t * ostride] = ts;
    }
}

__global__ __launch_bounds__(128)
void sopa_scan(const int* __restrict__ input_len,
               const float* __restrict__ epsilon,
               float* __restrict__ out) {
    extern __shared__ char ssm[];
    const uint32_t sb = smem_to_u32(ssm);
    const int tidx = threadIdx.x;
    const int b    = blockIdx.x >> 1;
    const int half = blockIdx.x & 1;
    const int sub  = tidx >> 6;         // 0 or 1 within the half
    const int ln   = tidx & 63;         // pattern index within group
    const int g    = half * 2 + sub;    // group 0..3
    const int n    = (g << 6) | ln;

    switch (g) {
        case 0: scan_body<3, 6>(b, n, 0    + ln * 6,  input_len, epsilon, out, ssm, sb, tidx); break;
        case 1: scan_body<4, 8>(b, n, 384  + ln * 8,  input_len, epsilon, out, ssm, sb, tidx); break;
        case 2: scan_body<5, 10>(b, n, 896  + ln * 10, input_len, epsilon, out, ssm, sb, tidx); break;
        default: scan_body<6, 12>(b, n, 1536 + ln * 12, input_len, epsilon, out, ssm, sb, tidx); break;
    }
}

// ===========================================================================
extern "C" void kernel_launch(void* const* d_in, const int* in_sizes, int n_in,
                              void* d_out, int out_size) {
    const float* x         = (const float*)d_in[0];   // (L,B,D) f32
    const int*   input_len = (const int*)  d_in[1];   // (B,)   i32
    const float* diags     = (const float*)d_in[2];   // (E,D)  f32
    const float* bias      = (const float*)d_in[3];   // (E,1)  f32
    const float* epsilon   = (const float*)d_in[4];   // (N,P-1) f32
    float*       out       = (float*)d_out;           // (L,B,N) f32

    cudaFuncSetAttribute(sopa_gemm_mma, cudaFuncAttributeMaxDynamicSharedMemorySize,
                         SMEM_BYTES);
    cudaFuncSetAttribute(sopa_scan, cudaFuncAttributeMaxDynamicSharedMemorySize,
                         SCAN_SMEM);

    __half *xhi, *xlo;
    cudaGetSymbolAddress((void**)&xhi, g_xhi);
    cudaGetSymbolAddress((void**)&xlo, g_xlo);

    cvt_split_tiled<<<M_ * 32 / 256, 256>>>(x, xhi, xlo);   // 4096 blocks
    repack_w_tiled<<<E3_, 32>>>(diags, bias);

    dim3 ggrid(E3_ / 128, M_ / 128);   // (18, 256)
    sopa_gemm_mma<<<ggrid, 512, SMEM_BYTES>>>();
    sopa_scan<<<128, 128, SCAN_SMEM>>>(input_len, epsilon, out);
}